// round 6
// baseline (speedup 1.0000x reference)
#include <cuda_runtime.h>
#include <cuda_bf16.h>
#include <math.h>

#define N_NODES 50000
#define N_EDGES 800000
#define HIDDEN  128
#define N_REL   64

// ---------------- device scratch ----------------
__device__ float g_QKV[N_NODES * 384];     // q | k | v per node, stride 384
__device__ float g_AO[N_NODES * HIDDEN];   // attention output before Wo
__device__ float g_Bpack[128 * 384];       // [Wq_top | Wk_top | Wv]
__device__ float g_biasp[384];             // [cq | ck | bv]
__device__ int   g_cnt[N_NODES];
__device__ int   g_start[N_NODES + 1];
__device__ int   g_fill[N_NODES];
__device__ int2  g_sorted[N_EDGES];        // (src, type) sorted by dst

// ---------------- pack B: coalesced, grid-wide ----------------
__global__ void pack_kernel(const float* __restrict__ Wq,
                            const float* __restrict__ Wk,
                            const float* __restrict__ Wv) {
    int idx = blockIdx.x * blockDim.x + threadIdx.x;
    if (idx >= 128 * 384) return;
    int i = idx / 384, j = idx - i * 384;
    float v;
    if (j < 128)      v = Wq[i * 128 + j];
    else if (j < 256) v = Wk[i * 128 + (j - 128)];
    else              v = Wv[i * 128 + (j - 256)];
    g_Bpack[idx] = v;
}

// ---------------- bias: fold query into q/k biases ----------------
__global__ void bias_kernel(const float* __restrict__ qe,
                            const float* __restrict__ Wq, const float* __restrict__ bq,
                            const float* __restrict__ Wk, const float* __restrict__ bk,
                            const float* __restrict__ bv) {
    __shared__ float qs[128];
    int j = threadIdx.x;
    qs[j] = qe[j];
    __syncthreads();
    int b = blockIdx.x;
    if (b == 0) {
        float c = bq[j];
        #pragma unroll 4
        for (int i = 0; i < 128; i++) c += qs[i] * Wq[(128 + i) * 128 + j];
        g_biasp[j] = c;
    } else if (b == 1) {
        float c = bk[j];
        #pragma unroll 4
        for (int i = 0; i < 128; i++) c += qs[i] * Wk[(128 + i) * 128 + j];
        g_biasp[128 + j] = c;
    } else {
        g_biasp[256 + j] = bv[j];
    }
}

// ---------------- fp32 GEMM, f32x2 FMA, 512 threads, 4x8 microtile ----------------
// C[M,N] = A[M,128] @ B[128,N] + bias. BM=128, BN=128, BK=32.
// A staged transposed (Ast[k][m]) -> mainloop A read is one warp-uniform LDS.128.
// B pairs feed fma.rn.f32x2 directly; accumulators are N-paired for coalesced stores.
__global__ __launch_bounds__(512) void gemm_kernel(
        const float* __restrict__ A, const float* __restrict__ B,
        const float* __restrict__ bias, float* __restrict__ C,
        int M, int N) {
    __shared__ float Ast[32][132];   // [k][m], pad 132 (16B-aligned rows)
    __shared__ float Bs[32][128];    // [k][n]
    const int tid = threadIdx.x;
    const int tx = tid & 15;         // 0..15 -> 8 cols
    const int ty = tid >> 4;         // 0..31 -> 4 rows
    const int m0 = blockIdx.x * 128;
    const int n0 = blockIdx.y * 128;

    unsigned long long acc[4][4];    // [row][colpair]
    #pragma unroll
    for (int i = 0; i < 4; i++)
        #pragma unroll
        for (int j = 0; j < 4; j++) acc[i][j] = 0ull;

    for (int k0 = 0; k0 < 128; k0 += 32) {
        // stage A tile 128x32 transposed: coalesced float4 along k, scalar STS
        #pragma unroll
        for (int it = 0; it < 2; it++) {
            int idx = tid + it * 512;          // 0..1023
            int row = idx >> 3;                // 0..127 (m)
            int c4  = idx & 7;                 // k offset c4*4
            float4 a = make_float4(0.f, 0.f, 0.f, 0.f);
            if (m0 + row < M)
                a = *(const float4*)(A + (size_t)(m0 + row) * 128 + k0 + c4 * 4);
            Ast[c4 * 4 + 0][row] = a.x;
            Ast[c4 * 4 + 1][row] = a.y;
            Ast[c4 * 4 + 2][row] = a.z;
            Ast[c4 * 4 + 3][row] = a.w;
        }
        // stage B tile 32x128
        #pragma unroll
        for (int it = 0; it < 2; it++) {
            int idx = tid + it * 512;          // 0..1023
            int row = idx >> 5;                // 0..31 (k)
            int c4  = idx & 31;
            float4 b = *(const float4*)(B + (size_t)(k0 + row) * N + n0 + c4 * 4);
            *(float4*)&Bs[row][c4 * 4] = b;
        }
        __syncthreads();

        #pragma unroll
        for (int k = 0; k < 32; k++) {
            // A: 4 row values, warp-uniform broadcast LDS.128
            float4 a = *(const float4*)&Ast[k][ty * 4];
            unsigned long long ap[4];
            asm("mov.b64 %0, {%1, %1};" : "=l"(ap[0]) : "r"(__float_as_uint(a.x)));
            asm("mov.b64 %0, {%1, %1};" : "=l"(ap[1]) : "r"(__float_as_uint(a.y)));
            asm("mov.b64 %0, {%1, %1};" : "=l"(ap[2]) : "r"(__float_as_uint(a.z)));
            asm("mov.b64 %0, {%1, %1};" : "=l"(ap[3]) : "r"(__float_as_uint(a.w)));
            // B: 8 consecutive floats = 4 ready-made f32x2 pairs
            ulonglong2 b01 = *(const ulonglong2*)&Bs[k][tx * 8];
            ulonglong2 b23 = *(const ulonglong2*)&Bs[k][tx * 8 + 4];
            unsigned long long bp[4] = {b01.x, b01.y, b23.x, b23.y};
            #pragma unroll
            for (int i = 0; i < 4; i++)
                #pragma unroll
                for (int j = 0; j < 4; j++)
                    asm("fma.rn.f32x2 %0, %1, %2, %0;"
                        : "+l"(acc[i][j]) : "l"(ap[i]), "l"(bp[j]));
        }
        __syncthreads();
    }

    // epilogue: fully coalesced STG.128 (warp covers 2 rows x 128 cols)
    const int n = n0 + tx * 8;
    float4 bi0 = *(const float4*)&bias[n];
    float4 bi1 = *(const float4*)&bias[n + 4];
    #pragma unroll
    for (int i = 0; i < 4; i++) {
        int m = m0 + ty * 4 + i;
        if (m >= M) break;
        float2 v0 = *(float2*)&acc[i][0];
        float2 v1 = *(float2*)&acc[i][1];
        float2 v2 = *(float2*)&acc[i][2];
        float2 v3 = *(float2*)&acc[i][3];
        float4 o0 = make_float4(v0.x + bi0.x, v0.y + bi0.y, v1.x + bi0.z, v1.y + bi0.w);
        float4 o1 = make_float4(v2.x + bi1.x, v2.y + bi1.y, v3.x + bi1.z, v3.y + bi1.w);
        *(float4*)(C + (size_t)m * N + n)     = o0;
        *(float4*)(C + (size_t)m * N + n + 4) = o1;
    }
}

// ---------------- counting sort by dst ----------------
__global__ void zero_cnt_kernel() {
    int i = blockIdx.x * blockDim.x + threadIdx.x;
    if (i < N_NODES) g_cnt[i] = 0;
}

__global__ void hist_kernel(const int* __restrict__ dst) {
    int e = blockIdx.x * blockDim.x + threadIdx.x;
    if (e < N_EDGES) atomicAdd(&g_cnt[dst[e]], 1);
}

__global__ void scan_kernel() {
    __shared__ int warp_sums[32];
    __shared__ int s_off;
    const int t = threadIdx.x;
    const int lane = t & 31, wid = t >> 5;
    if (t == 0) s_off = 0;
    __syncthreads();
    for (int base = 0; base < N_NODES; base += 1024) {
        int i = base + t;
        int v = (i < N_NODES) ? g_cnt[i] : 0;
        int x = v;
        #pragma unroll
        for (int d = 1; d < 32; d <<= 1) {
            int y = __shfl_up_sync(0xffffffffu, x, d);
            if (lane >= d) x += y;
        }
        if (lane == 31) warp_sums[wid] = x;
        __syncthreads();
        if (wid == 0) {
            int s = warp_sums[lane];
            #pragma unroll
            for (int d = 1; d < 32; d <<= 1) {
                int y = __shfl_up_sync(0xffffffffu, s, d);
                if (lane >= d) s += y;
            }
            warp_sums[lane] = s;
        }
        __syncthreads();
        int warp_off = (wid > 0) ? warp_sums[wid - 1] : 0;
        int inc = x + warp_off;
        int total = warp_sums[31];
        int excl = s_off + inc - v;
        if (i < N_NODES) { g_start[i] = excl; g_fill[i] = excl; }
        __syncthreads();
        if (t == 0) s_off += total;
        __syncthreads();
    }
    if (t == 0) g_start[N_NODES] = s_off;
}

__global__ void scatter_kernel(const int* __restrict__ src,
                               const int* __restrict__ dst,
                               const int* __restrict__ typ) {
    int e = blockIdx.x * blockDim.x + threadIdx.x;
    if (e >= N_EDGES) return;
    int d = dst[e];
    int pos = atomicAdd(&g_fill[d], 1);
    g_sorted[pos] = make_int2(src[e], typ[e]);
}

// ---------------- warp-per-dst softmax aggregation ----------------
__global__ void agg_kernel(const float* __restrict__ rel) {
    int warp = (blockIdx.x * blockDim.x + threadIdx.x) >> 5;
    int lane = threadIdx.x & 31;
    if (warp >= N_NODES) return;
    const int dst = warp;
    const float4* __restrict__ QKV4 = (const float4*)g_QKV;  // stride 96 float4/node
    const float4* __restrict__ R4   = (const float4*)rel;    // stride 32 float4/rel

    float4 qv = QKV4[(size_t)dst * 96 + lane];
    int beg = g_start[dst], end = g_start[dst + 1];

    float4 acc = make_float4(0.f, 0.f, 0.f, 0.f);
    float sacc = 0.f;

    for (int e0 = beg; e0 < end; e0 += 32) {
        int2 er = make_int2(0, 0);
        if (e0 + lane < end) er = g_sorted[e0 + lane];
        int cnt = min(32, end - e0);
        if (cnt == 32) {
            #pragma unroll 4
            for (int i = 0; i < 32; i++) {
                int src = __shfl_sync(0xffffffffu, er.x, i);
                int typ = __shfl_sync(0xffffffffu, er.y, i);
                float4 kv = QKV4[(size_t)src * 96 + 32 + lane];
                float4 vv = QKV4[(size_t)src * 96 + 64 + lane];
                float4 rb = R4[typ * 32 + lane];
                float p = qv.x * (kv.x + rb.x) + qv.y * (kv.y + rb.y)
                        + qv.z * (kv.z + rb.z) + qv.w * (kv.w + rb.w);
                p += __shfl_xor_sync(0xffffffffu, p, 1);
                p += __shfl_xor_sync(0xffffffffu, p, 2);
                float w = __expf(p * 0.25f);
                sacc += w;
                acc.x += w * vv.x; acc.y += w * vv.y;
                acc.z += w * vv.z; acc.w += w * vv.w;
            }
        } else {
            for (int i = 0; i < cnt; i++) {
                int src = __shfl_sync(0xffffffffu, er.x, i);
                int typ = __shfl_sync(0xffffffffu, er.y, i);
                float4 kv = QKV4[(size_t)src * 96 + 32 + lane];
                float4 vv = QKV4[(size_t)src * 96 + 64 + lane];
                float4 rb = R4[typ * 32 + lane];
                float p = qv.x * (kv.x + rb.x) + qv.y * (kv.y + rb.y)
                        + qv.z * (kv.z + rb.z) + qv.w * (kv.w + rb.w);
                p += __shfl_xor_sync(0xffffffffu, p, 1);
                p += __shfl_xor_sync(0xffffffffu, p, 2);
                float w = __expf(p * 0.25f);
                sacc += w;
                acc.x += w * vv.x; acc.y += w * vv.y;
                acc.z += w * vv.z; acc.w += w * vv.w;
            }
        }
    }
    float inv = 1.0f / (sacc + 1e-8f);
    float4 o = make_float4(acc.x * inv, acc.y * inv, acc.z * inv, acc.w * inv);
    ((float4*)g_AO)[(size_t)dst * 32 + lane] = o;
}

// ---------------- launch ----------------
extern "C" void kernel_launch(void* const* d_in, const int* in_sizes, int n_in,
                              void* d_out, int out_size) {
    const float* node_features = (const float*)d_in[0];
    const float* query_emb     = (const float*)d_in[1];
    const float* rel_emb       = (const float*)d_in[2];
    const float* Wq            = (const float*)d_in[3];
    const float* bq            = (const float*)d_in[4];
    const float* Wk            = (const float*)d_in[5];
    const float* bk            = (const float*)d_in[6];
    const float* Wv            = (const float*)d_in[7];
    const float* bv            = (const float*)d_in[8];
    const float* Wo            = (const float*)d_in[9];
    const float* bo            = (const float*)d_in[10];
    const int*   edge_index    = (const int*)d_in[11];
    const int*   edge_type     = (const int*)d_in[12];
    float* out = (float*)d_out;

    const int* e_src = edge_index;
    const int* e_dst = edge_index + N_EDGES;

    float* d_QKV; cudaGetSymbolAddress((void**)&d_QKV, g_QKV);
    float* d_AO;  cudaGetSymbolAddress((void**)&d_AO,  g_AO);
    float* d_Bp;  cudaGetSymbolAddress((void**)&d_Bp,  g_Bpack);
    float* d_bp;  cudaGetSymbolAddress((void**)&d_bp,  g_biasp);

    pack_kernel<<<(128 * 384 + 255) / 256, 256>>>(Wq, Wk, Wv);
    bias_kernel<<<3, 128>>>(query_emb, Wq, bq, Wk, bk, bv);
    zero_cnt_kernel<<<(N_NODES + 255) / 256, 256>>>();

    // fused QKV projection: 50000x384
    {
        dim3 grid((N_NODES + 127) / 128, 3);
        gemm_kernel<<<grid, 512>>>(node_features, d_Bp, d_bp, d_QKV, N_NODES, 384);
    }

    hist_kernel<<<(N_EDGES + 255) / 256, 256>>>(e_dst);
    scan_kernel<<<1, 1024>>>();
    scatter_kernel<<<(N_EDGES + 255) / 256, 256>>>(e_src, e_dst, edge_type);

    agg_kernel<<<(N_NODES * 32 + 255) / 256, 256>>>(rel_emb);

    // output projection: 50000x128 @ 128x128 + bo
    {
        dim3 grid((N_NODES + 127) / 128, 1);
        gemm_kernel<<<grid, 512>>>(d_AO, Wo, bo, out, N_NODES, 128);
    }
}

// round 7
// speedup vs baseline: 1.3246x; 1.3246x over previous
#include <cuda_runtime.h>
#include <cuda_bf16.h>
#include <math.h>

#define N_NODES 50000
#define N_EDGES 800000
#define HIDDEN  128
#define N_REL   64

// ---------------- device scratch ----------------
__device__ float g_QKV[N_NODES * 384];     // q | k | v per node, stride 384
__device__ float g_AO[N_NODES * HIDDEN];   // attention output before Wo
__device__ float g_Bpack[128 * 384];       // [Wq_top | Wk_top | Wv]
__device__ float g_biasp[384];             // [cq | ck | bv]
__device__ int   g_cnt[N_NODES];
__device__ int   g_start[N_NODES + 1];
__device__ int   g_fill[N_NODES];
__device__ int2  g_sorted[N_EDGES];        // (src, type) sorted by dst

// ---------------- pack B: coalesced, grid-wide ----------------
__global__ void pack_kernel(const float* __restrict__ Wq,
                            const float* __restrict__ Wk,
                            const float* __restrict__ Wv) {
    int idx = blockIdx.x * blockDim.x + threadIdx.x;
    if (idx >= 128 * 384) return;
    int i = idx / 384, j = idx - i * 384;
    float v;
    if (j < 128)      v = Wq[i * 128 + j];
    else if (j < 256) v = Wk[i * 128 + (j - 128)];
    else              v = Wv[i * 128 + (j - 256)];
    g_Bpack[idx] = v;
}

// ---------------- bias: fold query into q/k biases ----------------
__global__ void bias_kernel(const float* __restrict__ qe,
                            const float* __restrict__ Wq, const float* __restrict__ bq,
                            const float* __restrict__ Wk, const float* __restrict__ bk,
                            const float* __restrict__ bv) {
    __shared__ float qs[128];
    int j = threadIdx.x;
    qs[j] = qe[j];
    __syncthreads();
    int b = blockIdx.x;
    if (b == 0) {
        float c = bq[j];
        #pragma unroll 4
        for (int i = 0; i < 128; i++) c += qs[i] * Wq[(128 + i) * 128 + j];
        g_biasp[j] = c;
    } else if (b == 1) {
        float c = bk[j];
        #pragma unroll 4
        for (int i = 0; i < 128; i++) c += qs[i] * Wk[(128 + i) * 128 + j];
        g_biasp[128 + j] = c;
    } else {
        g_biasp[256 + j] = bv[j];
    }
}

// ---------------- fp32 GEMM, f32x2 FMA, 256 threads, 8x8 microtile ----------------
// C[M,N] = A[M,128] @ B[128,N] + bias. BM=128, BN=128, BK=32.
// A staged transposed (Ast[k][m]) -> A read = 2 near-broadcast LDS.128.
// B pairs feed fma.rn.f32x2 directly. launch_bounds(256,2) -> 2 CTAs/SM.
__global__ __launch_bounds__(256, 2) void gemm_kernel(
        const float* __restrict__ A, const float* __restrict__ B,
        const float* __restrict__ bias, float* __restrict__ C,
        int M, int N) {
    __shared__ float Ast[32][132];   // [k][m], padded to 132
    __shared__ float Bs[32][128];    // [k][n]
    const int tid = threadIdx.x;
    const int tx = tid & 15;         // 0..15 -> 8 cols
    const int ty = tid >> 4;         // 0..15 -> 8 rows
    const int m0 = blockIdx.x * 128;
    const int n0 = blockIdx.y * 128;

    unsigned long long acc[8][4];    // [row][colpair]
    #pragma unroll
    for (int i = 0; i < 8; i++)
        #pragma unroll
        for (int j = 0; j < 4; j++) acc[i][j] = 0ull;

    for (int k0 = 0; k0 < 128; k0 += 32) {
        // stage A tile 128x32 transposed: coalesced float4 loads, scalar STS
        #pragma unroll
        for (int it = 0; it < 4; it++) {
            int idx = tid + it * 256;          // 0..1023
            int row = idx >> 3;                // 0..127 (m)
            int c4  = idx & 7;                 // k offset c4*4
            float4 a = make_float4(0.f, 0.f, 0.f, 0.f);
            if (m0 + row < M)
                a = *(const float4*)(A + (size_t)(m0 + row) * 128 + k0 + c4 * 4);
            Ast[c4 * 4 + 0][row] = a.x;
            Ast[c4 * 4 + 1][row] = a.y;
            Ast[c4 * 4 + 2][row] = a.z;
            Ast[c4 * 4 + 3][row] = a.w;
        }
        // stage B tile 32x128
        #pragma unroll
        for (int it = 0; it < 4; it++) {
            int idx = tid + it * 256;
            int row = idx >> 5;                // 0..31 (k)
            int c4  = idx & 31;
            float4 b = *(const float4*)(B + (size_t)(k0 + row) * N + n0 + c4 * 4);
            *(float4*)&Bs[row][c4 * 4] = b;
        }
        __syncthreads();

        #pragma unroll
        for (int k = 0; k < 32; k++) {
            // A: 8 row values via 2 near-broadcast LDS.128
            float4 a0 = *(const float4*)&Ast[k][ty * 8];
            float4 a1 = *(const float4*)&Ast[k][ty * 8 + 4];
            unsigned long long ap[8];
            asm("mov.b64 %0, {%1, %1};" : "=l"(ap[0]) : "r"(__float_as_uint(a0.x)));
            asm("mov.b64 %0, {%1, %1};" : "=l"(ap[1]) : "r"(__float_as_uint(a0.y)));
            asm("mov.b64 %0, {%1, %1};" : "=l"(ap[2]) : "r"(__float_as_uint(a0.z)));
            asm("mov.b64 %0, {%1, %1};" : "=l"(ap[3]) : "r"(__float_as_uint(a0.w)));
            asm("mov.b64 %0, {%1, %1};" : "=l"(ap[4]) : "r"(__float_as_uint(a1.x)));
            asm("mov.b64 %0, {%1, %1};" : "=l"(ap[5]) : "r"(__float_as_uint(a1.y)));
            asm("mov.b64 %0, {%1, %1};" : "=l"(ap[6]) : "r"(__float_as_uint(a1.z)));
            asm("mov.b64 %0, {%1, %1};" : "=l"(ap[7]) : "r"(__float_as_uint(a1.w)));
            // B: 8 consecutive floats = 4 ready-made f32x2 pairs
            ulonglong2 b01 = *(const ulonglong2*)&Bs[k][tx * 8];
            ulonglong2 b23 = *(const ulonglong2*)&Bs[k][tx * 8 + 4];
            unsigned long long bp[4] = {b01.x, b01.y, b23.x, b23.y};
            #pragma unroll
            for (int i = 0; i < 8; i++)
                #pragma unroll
                for (int j = 0; j < 4; j++)
                    asm("fma.rn.f32x2 %0, %1, %2, %0;"
                        : "+l"(acc[i][j]) : "l"(ap[i]), "l"(bp[j]));
        }
        __syncthreads();
    }

    // epilogue: coalesced STG.128
    const int n = n0 + tx * 8;
    float4 bi0 = *(const float4*)&bias[n];
    float4 bi1 = *(const float4*)&bias[n + 4];
    #pragma unroll
    for (int i = 0; i < 8; i++) {
        int m = m0 + ty * 8 + i;
        if (m >= M) break;
        float2 v0 = *(float2*)&acc[i][0];
        float2 v1 = *(float2*)&acc[i][1];
        float2 v2 = *(float2*)&acc[i][2];
        float2 v3 = *(float2*)&acc[i][3];
        float4 o0 = make_float4(v0.x + bi0.x, v0.y + bi0.y, v1.x + bi0.z, v1.y + bi0.w);
        float4 o1 = make_float4(v2.x + bi1.x, v2.y + bi1.y, v3.x + bi1.z, v3.y + bi1.w);
        *(float4*)(C + (size_t)m * N + n)     = o0;
        *(float4*)(C + (size_t)m * N + n + 4) = o1;
    }
}

// ---------------- counting sort by dst ----------------
__global__ void zero_cnt_kernel() {
    int i = blockIdx.x * blockDim.x + threadIdx.x;
    if (i < N_NODES) g_cnt[i] = 0;
}

__global__ void hist_kernel(const int* __restrict__ dst) {
    int e = blockIdx.x * blockDim.x + threadIdx.x;
    if (e < N_EDGES) atomicAdd(&g_cnt[dst[e]], 1);
}

__global__ void scan_kernel() {
    __shared__ int warp_sums[32];
    __shared__ int s_off;
    const int t = threadIdx.x;
    const int lane = t & 31, wid = t >> 5;
    if (t == 0) s_off = 0;
    __syncthreads();
    for (int base = 0; base < N_NODES; base += 1024) {
        int i = base + t;
        int v = (i < N_NODES) ? g_cnt[i] : 0;
        int x = v;
        #pragma unroll
        for (int d = 1; d < 32; d <<= 1) {
            int y = __shfl_up_sync(0xffffffffu, x, d);
            if (lane >= d) x += y;
        }
        if (lane == 31) warp_sums[wid] = x;
        __syncthreads();
        if (wid == 0) {
            int s = warp_sums[lane];
            #pragma unroll
            for (int d = 1; d < 32; d <<= 1) {
                int y = __shfl_up_sync(0xffffffffu, s, d);
                if (lane >= d) s += y;
            }
            warp_sums[lane] = s;
        }
        __syncthreads();
        int warp_off = (wid > 0) ? warp_sums[wid - 1] : 0;
        int inc = x + warp_off;
        int total = warp_sums[31];
        int excl = s_off + inc - v;
        if (i < N_NODES) { g_start[i] = excl; g_fill[i] = excl; }
        __syncthreads();
        if (t == 0) s_off += total;
        __syncthreads();
    }
    if (t == 0) g_start[N_NODES] = s_off;
}

__global__ void scatter_kernel(const int* __restrict__ src,
                               const int* __restrict__ dst,
                               const int* __restrict__ typ) {
    int e = blockIdx.x * blockDim.x + threadIdx.x;
    if (e >= N_EDGES) return;
    int d = dst[e];
    int pos = atomicAdd(&g_fill[d], 1);
    g_sorted[pos] = make_int2(src[e], typ[e]);
}

// ---------------- warp-per-dst softmax aggregation ----------------
__global__ void agg_kernel(const float* __restrict__ rel) {
    int warp = (blockIdx.x * blockDim.x + threadIdx.x) >> 5;
    int lane = threadIdx.x & 31;
    if (warp >= N_NODES) return;
    const int dst = warp;
    const float4* __restrict__ QKV4 = (const float4*)g_QKV;  // stride 96 float4/node
    const float4* __restrict__ R4   = (const float4*)rel;    // stride 32 float4/rel

    float4 qv = QKV4[(size_t)dst * 96 + lane];
    int beg = g_start[dst], end = g_start[dst + 1];

    float4 acc = make_float4(0.f, 0.f, 0.f, 0.f);
    float sacc = 0.f;

    for (int e0 = beg; e0 < end; e0 += 32) {
        int2 er = make_int2(0, 0);
        if (e0 + lane < end) er = g_sorted[e0 + lane];
        int cnt = min(32, end - e0);
        if (cnt == 32) {
            #pragma unroll 4
            for (int i = 0; i < 32; i++) {
                int src = __shfl_sync(0xffffffffu, er.x, i);
                int typ = __shfl_sync(0xffffffffu, er.y, i);
                float4 kv = QKV4[(size_t)src * 96 + 32 + lane];
                float4 vv = QKV4[(size_t)src * 96 + 64 + lane];
                float4 rb = R4[typ * 32 + lane];
                float p = qv.x * (kv.x + rb.x) + qv.y * (kv.y + rb.y)
                        + qv.z * (kv.z + rb.z) + qv.w * (kv.w + rb.w);
                p += __shfl_xor_sync(0xffffffffu, p, 1);
                p += __shfl_xor_sync(0xffffffffu, p, 2);
                float w = __expf(p * 0.25f);
                sacc += w;
                acc.x += w * vv.x; acc.y += w * vv.y;
                acc.z += w * vv.z; acc.w += w * vv.w;
            }
        } else {
            for (int i = 0; i < cnt; i++) {
                int src = __shfl_sync(0xffffffffu, er.x, i);
                int typ = __shfl_sync(0xffffffffu, er.y, i);
                float4 kv = QKV4[(size_t)src * 96 + 32 + lane];
                float4 vv = QKV4[(size_t)src * 96 + 64 + lane];
                float4 rb = R4[typ * 32 + lane];
                float p = qv.x * (kv.x + rb.x) + qv.y * (kv.y + rb.y)
                        + qv.z * (kv.z + rb.z) + qv.w * (kv.w + rb.w);
                p += __shfl_xor_sync(0xffffffffu, p, 1);
                p += __shfl_xor_sync(0xffffffffu, p, 2);
                float w = __expf(p * 0.25f);
                sacc += w;
                acc.x += w * vv.x; acc.y += w * vv.y;
                acc.z += w * vv.z; acc.w += w * vv.w;
            }
        }
    }
    float inv = 1.0f / (sacc + 1e-8f);
    float4 o = make_float4(acc.x * inv, acc.y * inv, acc.z * inv, acc.w * inv);
    ((float4*)g_AO)[(size_t)dst * 32 + lane] = o;
}

// ---------------- launch ----------------
extern "C" void kernel_launch(void* const* d_in, const int* in_sizes, int n_in,
                              void* d_out, int out_size) {
    const float* node_features = (const float*)d_in[0];
    const float* query_emb     = (const float*)d_in[1];
    const float* rel_emb       = (const float*)d_in[2];
    const float* Wq            = (const float*)d_in[3];
    const float* bq            = (const float*)d_in[4];
    const float* Wk            = (const float*)d_in[5];
    const float* bk            = (const float*)d_in[6];
    const float* Wv            = (const float*)d_in[7];
    const float* bv            = (const float*)d_in[8];
    const float* Wo            = (const float*)d_in[9];
    const float* bo            = (const float*)d_in[10];
    const int*   edge_index    = (const int*)d_in[11];
    const int*   edge_type     = (const int*)d_in[12];
    float* out = (float*)d_out;

    const int* e_src = edge_index;
    const int* e_dst = edge_index + N_EDGES;

    float* d_QKV; cudaGetSymbolAddress((void**)&d_QKV, g_QKV);
    float* d_AO;  cudaGetSymbolAddress((void**)&d_AO,  g_AO);
    float* d_Bp;  cudaGetSymbolAddress((void**)&d_Bp,  g_Bpack);
    float* d_bp;  cudaGetSymbolAddress((void**)&d_bp,  g_biasp);

    pack_kernel<<<(128 * 384 + 255) / 256, 256>>>(Wq, Wk, Wv);
    bias_kernel<<<3, 128>>>(query_emb, Wq, bq, Wk, bk, bv);
    zero_cnt_kernel<<<(N_NODES + 255) / 256, 256>>>();

    // fused QKV projection: 50000x384
    {
        dim3 grid((N_NODES + 127) / 128, 3);
        gemm_kernel<<<grid, 256>>>(node_features, d_Bp, d_bp, d_QKV, N_NODES, 384);
    }

    hist_kernel<<<(N_EDGES + 255) / 256, 256>>>(e_dst);
    scan_kernel<<<1, 1024>>>();
    scatter_kernel<<<(N_EDGES + 255) / 256, 256>>>(e_src, e_dst, edge_type);

    agg_kernel<<<(N_NODES * 32 + 255) / 256, 256>>>(rel_emb);

    // output projection: 50000x128 @ 128x128 + bo
    {
        dim3 grid((N_NODES + 127) / 128, 1);
        gemm_kernel<<<grid, 256>>>(d_AO, Wo, bo, out, N_NODES, 128);
    }
}

// round 11
// speedup vs baseline: 1.4197x; 1.0718x over previous
#include <cuda_runtime.h>
#include <cuda_bf16.h>
#include <math.h>
#include <stdint.h>

#define N_NODES 50000
#define N_EDGES 800000
#define HIDDEN  128
#define N_REL   64

// ---------------- device scratch ----------------
__device__ float g_QKV[N_NODES * 384];          // q | k | v per node, stride 384
__device__ float g_AO[N_NODES * HIDDEN];        // attention output before Wo
__device__ float g_biasp[384];                  // [cq | ck | bv]
__device__ int   g_cnt[N_NODES];
__device__ int   g_start[N_NODES + 1];
__device__ int   g_fill[N_NODES];
__device__ int2  g_sorted[N_EDGES];             // (src, type) sorted by dst
// split-precision bf16 operands
__device__ __nv_bfloat16 g_Ahi[N_NODES * 128];
__device__ __nv_bfloat16 g_Alo[N_NODES * 128];
__device__ __nv_bfloat16 g_AOhi[N_NODES * 128];
__device__ __nv_bfloat16 g_AOlo[N_NODES * 128];
__device__ __nv_bfloat16 g_Bthi[384 * 128];     // QKV weights, [n][k] K-major
__device__ __nv_bfloat16 g_Btlo[384 * 128];
__device__ __nv_bfloat16 g_Wohi[128 * 128];     // Wo^T, [n][k] K-major
__device__ __nv_bfloat16 g_Wolo[128 * 128];

// ---------------- PTX helpers (baseline ISA only: ldmatrix + mma.sync) ----------------
__device__ __forceinline__ uint32_t smem_u32(const void* p) {
    uint32_t a;
    asm("{ .reg .u64 t; cvta.to.shared.u64 t, %1; cvt.u32.u64 %0, t; }" : "=r"(a) : "l"(p));
    return a;
}

#define LDSM_X4(r0, r1, r2, r3, addr)                                              \
    asm volatile("ldmatrix.sync.aligned.m8n8.x4.shared.b16 {%0,%1,%2,%3}, [%4];"   \
                 : "=r"(r0), "=r"(r1), "=r"(r2), "=r"(r3) : "r"(addr))

#define MMA16816(c, a, b)                                                          \
    asm volatile("mma.sync.aligned.m16n8k16.row.col.f32.bf16.bf16.f32 "            \
                 "{%0,%1,%2,%3},{%4,%5,%6,%7},{%8,%9},{%0,%1,%2,%3};"              \
                 : "+f"((c)[0]), "+f"((c)[1]), "+f"((c)[2]), "+f"((c)[3])          \
                 : "r"((a)[0]), "r"((a)[1]), "r"((a)[2]), "r"((a)[3]),             \
                   "r"((b)[0]), "r"((b)[1]))

// ---------------- fp32 -> (hi, lo) bf16 split ----------------
__global__ void cvt_split4(const float* __restrict__ X,
                           __nv_bfloat16* __restrict__ hi,
                           __nv_bfloat16* __restrict__ lo, int n4) {
    int i = blockIdx.x * blockDim.x + threadIdx.x;
    if (i >= n4) return;
    float4 x = ((const float4*)X)[i];
    __nv_bfloat16 h0 = __float2bfloat16(x.x), h1 = __float2bfloat16(x.y);
    __nv_bfloat16 h2 = __float2bfloat16(x.z), h3 = __float2bfloat16(x.w);
    __nv_bfloat16 l0 = __float2bfloat16(x.x - __bfloat162float(h0));
    __nv_bfloat16 l1 = __float2bfloat16(x.y - __bfloat162float(h1));
    __nv_bfloat16 l2 = __float2bfloat16(x.z - __bfloat162float(h2));
    __nv_bfloat16 l3 = __float2bfloat16(x.w - __bfloat162float(h3));
    __nv_bfloat162* H = reinterpret_cast<__nv_bfloat162*>(hi + 4 * (size_t)i);
    __nv_bfloat162* L = reinterpret_cast<__nv_bfloat162*>(lo + 4 * (size_t)i);
    H[0] = __halves2bfloat162(h0, h1); H[1] = __halves2bfloat162(h2, h3);
    L[0] = __halves2bfloat162(l0, l1); L[1] = __halves2bfloat162(l2, l3);
}

// build Bt[n][k] = W(k, n) split into hi/lo (fused Wq|Wk|Wv transpose)
__global__ void cvt_Bt(const float* __restrict__ Wq, const float* __restrict__ Wk,
                       const float* __restrict__ Wv) {
    int idx = blockIdx.x * blockDim.x + threadIdx.x;
    if (idx >= 384 * 128) return;
    int n = idx >> 7, k = idx & 127;
    float v;
    if (n < 128)      v = Wq[k * 128 + n];
    else if (n < 256) v = Wk[k * 128 + (n - 128)];
    else              v = Wv[k * 128 + (n - 256)];
    __nv_bfloat16 h = __float2bfloat16(v);
    g_Bthi[idx] = h;
    g_Btlo[idx] = __float2bfloat16(v - __bfloat162float(h));
}

__global__ void cvt_Wot(const float* __restrict__ Wo) {
    int idx = blockIdx.x * blockDim.x + threadIdx.x;
    if (idx >= 128 * 128) return;
    int n = idx >> 7, k = idx & 127;
    float v = Wo[k * 128 + n];
    __nv_bfloat16 h = __float2bfloat16(v);
    g_Wohi[idx] = h;
    g_Wolo[idx] = __float2bfloat16(v - __bfloat162float(h));
}

// ---------------- bias: fold query into q/k biases ----------------
__global__ void bias_kernel(const float* __restrict__ qe,
                            const float* __restrict__ Wq, const float* __restrict__ bq,
                            const float* __restrict__ Wk, const float* __restrict__ bk,
                            const float* __restrict__ bv) {
    __shared__ float qs[128];
    int j = threadIdx.x;
    qs[j] = qe[j];
    __syncthreads();
    int b = blockIdx.x;
    if (b == 0) {
        float c = bq[j];
        #pragma unroll 4
        for (int i = 0; i < 128; i++) c += qs[i] * Wq[(128 + i) * 128 + j];
        g_biasp[j] = c;
    } else if (b == 1) {
        float c = bk[j];
        #pragma unroll 4
        for (int i = 0; i < 128; i++) c += qs[i] * Wk[(128 + i) * 128 + j];
        g_biasp[128 + j] = c;
    } else {
        g_biasp[256 + j] = bv[j];
    }
}

// ---------------- HMMA split-bf16 GEMM ----------------
// C[M,Nout] 128x128 tile = (Ahi+Alo)[M,128] @ (Bhi+Blo)[Nout,128]^T + bias
// D = Ahi*Bhi + Ahi*Blo + Alo*Bhi, fp32 accumulators.
// 256 threads = 8 warps (4m x 2n), warp tile 32x64, m16n8k16 fragments.
// K chunked by 32; smem stride 40 bf16 (80B) -> ldmatrix conflict-free.
#define SM_STRIDE 40
#define SM_TILE   (128 * SM_STRIDE)     // bf16 elems per tile buffer

__global__ __launch_bounds__(256) void gemm_mma(
        const __nv_bfloat16* __restrict__ Ahi, const __nv_bfloat16* __restrict__ Alo,
        const __nv_bfloat16* __restrict__ Bhi, const __nv_bfloat16* __restrict__ Blo,
        const float* __restrict__ bias, float* __restrict__ C,
        int M, int Nout) {
    __shared__ __align__(16) __nv_bfloat16 sm[4 * SM_TILE];  // Ahi|Alo|Bhi|Blo chunks
    const int tid = threadIdx.x;
    const int wid = tid >> 5, lane = tid & 31;
    const int m0 = blockIdx.x * 128, n0 = blockIdx.y * 128;
    const int wm = (wid & 3) * 32;          // warp m offset
    const int wn = (wid >> 2) * 64;         // warp n offset

    float acc[2][8][4];
    #pragma unroll
    for (int i = 0; i < 2; i++)
        #pragma unroll
        for (int j = 0; j < 8; j++)
            #pragma unroll
            for (int c = 0; c < 4; c++) acc[i][j][c] = 0.f;

    const uint32_t smb = smem_u32(sm);
    // ldmatrix lane address components
    const int a_row = lane & 15, a_c8 = (lane >> 4);             // A: x4 -> 16x16
    const int b_row = (lane & 7) | ((lane >> 4) << 3);           // B: x4 -> 2 n-frags
    const int b_c8 = (lane >> 3) & 1;

    for (int k0 = 0; k0 < 128; k0 += 32) {
        // ---- stage 4 chunk tiles (128 rows x 32 bf16 each) ----
        #pragma unroll
        for (int t = 0; t < 4; t++) {
            const __nv_bfloat16* P = (t == 0) ? Ahi : (t == 1) ? Alo : (t == 2) ? Bhi : Blo;
            const int base_row = (t < 2) ? m0 : n0;
            const bool isA = (t < 2);
            #pragma unroll
            for (int it = 0; it < 2; it++) {
                int idx = tid + it * 256;          // 0..511
                int row = idx >> 2, c8 = idx & 3;  // 16B chunk within row
                uint4 v = make_uint4(0u, 0u, 0u, 0u);
                if (!isA || base_row + row < M)
                    v = *(const uint4*)(P + (size_t)(base_row + row) * 128 + k0 + c8 * 8);
                *(uint4*)(sm + t * SM_TILE + row * SM_STRIDE + c8 * 8) = v;
            }
        }
        __syncthreads();

        // ---- 3 product passes on this k-chunk ----
        #pragma unroll
        for (int pass = 0; pass < 3; pass++) {
            const int tbA = (pass == 2) ? SM_TILE : 0;                 // Alo : Ahi
            const int tbB = (pass == 1) ? 3 * SM_TILE : 2 * SM_TILE;   // Blo : Bhi
            #pragma unroll
            for (int ks = 0; ks < 32; ks += 16) {
                uint32_t a[2][4], b[8][2];
                #pragma unroll
                for (int mi = 0; mi < 2; mi++) {
                    uint32_t addr = smb + 2 * (tbA + (wm + mi * 16 + a_row) * SM_STRIDE
                                               + ks + a_c8 * 8);
                    LDSM_X4(a[mi][0], a[mi][1], a[mi][2], a[mi][3], addr);
                }
                #pragma unroll
                for (int nb = 0; nb < 4; nb++) {
                    uint32_t addr = smb + 2 * (tbB + (wn + nb * 16 + b_row) * SM_STRIDE
                                               + ks + b_c8 * 8);
                    LDSM_X4(b[2 * nb][0], b[2 * nb][1], b[2 * nb + 1][0], b[2 * nb + 1][1], addr);
                }
                #pragma unroll
                for (int mi = 0; mi < 2; mi++)
                    #pragma unroll
                    for (int ni = 0; ni < 8; ni++)
                        MMA16816(acc[mi][ni], a[mi], b[ni]);
            }
        }
        __syncthreads();
    }

    // ---- epilogue: c{0,1} -> (row tq, col 2*tr), c{2,3} -> row+8 ----
    const int tq = lane >> 2, tr = lane & 3;
    #pragma unroll
    for (int ni = 0; ni < 8; ni++) {
        const int col = n0 + wn + ni * 8 + tr * 2;
        const float b0 = bias[col], b1 = bias[col + 1];
        #pragma unroll
        for (int mi = 0; mi < 2; mi++) {
            int mlow = m0 + wm + mi * 16 + tq;
            if (mlow < M) {
                float2 o = make_float2(acc[mi][ni][0] + b0, acc[mi][ni][1] + b1);
                *(float2*)(C + (size_t)mlow * Nout + col) = o;
            }
            int mhigh = mlow + 8;
            if (mhigh < M) {
                float2 o = make_float2(acc[mi][ni][2] + b0, acc[mi][ni][3] + b1);
                *(float2*)(C + (size_t)mhigh * Nout + col) = o;
            }
        }
    }
}

// ---------------- counting sort by dst ----------------
__global__ void zero_cnt_kernel() {
    int i = blockIdx.x * blockDim.x + threadIdx.x;
    if (i < N_NODES) g_cnt[i] = 0;
}

__global__ void hist_kernel(const int* __restrict__ dst) {
    int e = blockIdx.x * blockDim.x + threadIdx.x;
    if (e < N_EDGES) atomicAdd(&g_cnt[dst[e]], 1);
}

__global__ void scan_kernel() {
    __shared__ int warp_sums[32];
    __shared__ int s_off;
    const int t = threadIdx.x;
    const int lane = t & 31, wid = t >> 5;
    if (t == 0) s_off = 0;
    __syncthreads();
    for (int base = 0; base < N_NODES; base += 1024) {
        int i = base + t;
        int v = (i < N_NODES) ? g_cnt[i] : 0;
        int x = v;
        #pragma unroll
        for (int d = 1; d < 32; d <<= 1) {
            int y = __shfl_up_sync(0xffffffffu, x, d);
            if (lane >= d) x += y;
        }
        if (lane == 31) warp_sums[wid] = x;
        __syncthreads();
        if (wid == 0) {
            int s = warp_sums[lane];
            #pragma unroll
            for (int d = 1; d < 32; d <<= 1) {
                int y = __shfl_up_sync(0xffffffffu, s, d);
                if (lane >= d) s += y;
            }
            warp_sums[lane] = s;
        }
        __syncthreads();
        int warp_off = (wid > 0) ? warp_sums[wid - 1] : 0;
        int inc = x + warp_off;
        int total = warp_sums[31];
        int excl = s_off + inc - v;
        if (i < N_NODES) { g_start[i] = excl; g_fill[i] = excl; }
        __syncthreads();
        if (t == 0) s_off += total;
        __syncthreads();
    }
    if (t == 0) g_start[N_NODES] = s_off;
}

__global__ void scatter_kernel(const int* __restrict__ src,
                               const int* __restrict__ dst,
                               const int* __restrict__ typ) {
    int e = blockIdx.x * blockDim.x + threadIdx.x;
    if (e >= N_EDGES) return;
    int d = dst[e];
    int pos = atomicAdd(&g_fill[d], 1);
    g_sorted[pos] = make_int2(src[e], typ[e]);
}

// ---------------- warp-per-dst softmax aggregation (rel table in smem) ----------------
__global__ void agg_kernel(const float* __restrict__ rel) {
    __shared__ float srel[N_REL * 128];
    const int tid = threadIdx.x, wid = tid >> 5, lane = tid & 31;
    for (int i = tid; i < N_REL * 32; i += 256)
        ((float4*)srel)[i] = ((const float4*)rel)[i];
    __syncthreads();

    const float4* __restrict__ QKV4 = (const float4*)g_QKV;  // stride 96 float4/node

    for (int dst = blockIdx.x * 8 + wid; dst < N_NODES; dst += 8 * gridDim.x) {
        float4 qv = QKV4[(size_t)dst * 96 + lane];
        int beg = g_start[dst], end = g_start[dst + 1];

        float4 acc = make_float4(0.f, 0.f, 0.f, 0.f);
        float sacc = 0.f;

        for (int e0 = beg; e0 < end; e0 += 32) {
            int2 er = make_int2(0, 0);
            if (e0 + lane < end) er = g_sorted[e0 + lane];
            int cnt = min(32, end - e0);
            for (int i = 0; i < cnt; i++) {
                int src = __shfl_sync(0xffffffffu, er.x, i);
                int typ = __shfl_sync(0xffffffffu, er.y, i);
                float4 kv = QKV4[(size_t)src * 96 + 32 + lane];
                float4 vv = QKV4[(size_t)src * 96 + 64 + lane];
                float4 rb = *(const float4*)&srel[typ * 128 + lane * 4];
                float p = qv.x * (kv.x + rb.x) + qv.y * (kv.y + rb.y)
                        + qv.z * (kv.z + rb.z) + qv.w * (kv.w + rb.w);
                p += __shfl_xor_sync(0xffffffffu, p, 1);
                p += __shfl_xor_sync(0xffffffffu, p, 2);
                float w = __expf(p * 0.25f);
                sacc += w;
                acc.x += w * vv.x; acc.y += w * vv.y;
                acc.z += w * vv.z; acc.w += w * vv.w;
            }
        }
        float inv = 1.0f / (sacc + 1e-8f);
        float4 o = make_float4(acc.x * inv, acc.y * inv, acc.z * inv, acc.w * inv);
        ((float4*)g_AO)[(size_t)dst * 32 + lane] = o;
    }
}

// ---------------- launch ----------------
extern "C" void kernel_launch(void* const* d_in, const int* in_sizes, int n_in,
                              void* d_out, int out_size) {
    const float* node_features = (const float*)d_in[0];
    const float* query_emb     = (const float*)d_in[1];
    const float* rel_emb       = (const float*)d_in[2];
    const float* Wq            = (const float*)d_in[3];
    const float* bq            = (const float*)d_in[4];
    const float* Wk            = (const float*)d_in[5];
    const float* bk            = (const float*)d_in[6];
    const float* Wv            = (const float*)d_in[7];
    const float* bv            = (const float*)d_in[8];
    const float* Wo            = (const float*)d_in[9];
    const float* bo            = (const float*)d_in[10];
    const int*   edge_index    = (const int*)d_in[11];
    const int*   edge_type     = (const int*)d_in[12];
    float* out = (float*)d_out;

    const int* e_src = edge_index;
    const int* e_dst = edge_index + N_EDGES;

    float* d_QKV;  cudaGetSymbolAddress((void**)&d_QKV,  g_QKV);
    float* d_AO;   cudaGetSymbolAddress((void**)&d_AO,   g_AO);
    float* d_bp;   cudaGetSymbolAddress((void**)&d_bp,   g_biasp);
    __nv_bfloat16 *d_Ahi, *d_Alo, *d_AOhi, *d_AOlo, *d_Bthi, *d_Btlo, *d_Wohi, *d_Wolo;
    cudaGetSymbolAddress((void**)&d_Ahi,  g_Ahi);
    cudaGetSymbolAddress((void**)&d_Alo,  g_Alo);
    cudaGetSymbolAddress((void**)&d_AOhi, g_AOhi);
    cudaGetSymbolAddress((void**)&d_AOlo, g_AOlo);
    cudaGetSymbolAddress((void**)&d_Bthi, g_Bthi);
    cudaGetSymbolAddress((void**)&d_Btlo, g_Btlo);
    cudaGetSymbolAddress((void**)&d_Wohi, g_Wohi);
    cudaGetSymbolAddress((void**)&d_Wolo, g_Wolo);

    // prep: weight transposes + splits, bias fold, edge sort
    cvt_Bt<<<(384 * 128 + 255) / 256, 256>>>(Wq, Wk, Wv);
    cvt_Wot<<<(128 * 128 + 255) / 256, 256>>>(Wo);
    bias_kernel<<<3, 128>>>(query_emb, Wq, bq, Wk, bk, bv);
    zero_cnt_kernel<<<(N_NODES + 255) / 256, 256>>>();
    cvt_split4<<<(N_NODES * 128 / 4 + 255) / 256, 256>>>(node_features, d_Ahi, d_Alo,
                                                         N_NODES * 128 / 4);

    // fused QKV projection: 50000 x 384 (HMMA split-bf16)
    {
        dim3 grid((N_NODES + 127) / 128, 3);
        gemm_mma<<<grid, 256>>>(d_Ahi, d_Alo, d_Bthi, d_Btlo, d_bp, d_QKV,
                                N_NODES, 384);
    }

    hist_kernel<<<(N_EDGES + 255) / 256, 256>>>(e_dst);
    scan_kernel<<<1, 1024>>>();
    scatter_kernel<<<(N_EDGES + 255) / 256, 256>>>(e_src, e_dst, edge_type);

    agg_kernel<<<1024, 256>>>(rel_emb);

    // output projection: 50000 x 128 (HMMA split-bf16)
    cvt_split4<<<(N_NODES * 128 / 4 + 255) / 256, 256>>>(d_AO, d_AOhi, d_AOlo,
                                                         N_NODES * 128 / 4);
    {
        dim3 grid((N_NODES + 127) / 128, 1);
        gemm_mma<<<grid, 256>>>(d_AOhi, d_AOlo, d_Wohi, d_Wolo, bo, out,
                                N_NODES, 128);
    }
}

// round 13
// speedup vs baseline: 1.7582x; 1.2385x over previous
#include <cuda_runtime.h>
#include <cuda_bf16.h>
#include <math.h>
#include <stdint.h>

#define N_NODES 50000
#define N_EDGES 800000
#define HIDDEN  128
#define N_REL   64

// ---------------- device scratch ----------------
__device__ float g_QKV[N_NODES * 384];          // q | k | v per node, stride 384
__device__ float g_biasp[384];                  // [cq | ck | bv]
__device__ int   g_cnt[N_NODES];
__device__ int   g_excl[N_NODES];
__device__ int   g_bsum[64];
__device__ int   g_boff[64];
__device__ int   g_start[N_NODES + 1];
__device__ int   g_fill[N_NODES];
__device__ int2  g_sorted[N_EDGES];             // (src, type) sorted by dst
// split-precision bf16 operands
__device__ __nv_bfloat16 g_Ahi[N_NODES * 128];
__device__ __nv_bfloat16 g_Alo[N_NODES * 128];
__device__ __nv_bfloat16 g_AOhi[N_NODES * 128];
__device__ __nv_bfloat16 g_AOlo[N_NODES * 128];
__device__ __nv_bfloat16 g_Bthi[384 * 128];     // QKV weights, [n][k] K-major
__device__ __nv_bfloat16 g_Btlo[384 * 128];
__device__ __nv_bfloat16 g_Wohi[128 * 128];     // Wo^T, [n][k] K-major
__device__ __nv_bfloat16 g_Wolo[128 * 128];

// ---------------- PTX helpers (baseline ISA only) ----------------
__device__ __forceinline__ uint32_t smem_u32(const void* p) {
    uint32_t a;
    asm("{ .reg .u64 t; cvta.to.shared.u64 t, %1; cvt.u32.u64 %0, t; }" : "=r"(a) : "l"(p));
    return a;
}

#define LDSM_X4(r0, r1, r2, r3, addr)                                              \
    asm volatile("ldmatrix.sync.aligned.m8n8.x4.shared.b16 {%0,%1,%2,%3}, [%4];"   \
                 : "=r"(r0), "=r"(r1), "=r"(r2), "=r"(r3) : "r"(addr))

#define MMA16816(c, a, b)                                                          \
    asm volatile("mma.sync.aligned.m16n8k16.row.col.f32.bf16.bf16.f32 "            \
                 "{%0,%1,%2,%3},{%4,%5,%6,%7},{%8,%9},{%0,%1,%2,%3};"              \
                 : "+f"((c)[0]), "+f"((c)[1]), "+f"((c)[2]), "+f"((c)[3])          \
                 : "r"((a)[0]), "r"((a)[1]), "r"((a)[2]), "r"((a)[3]),             \
                   "r"((b)[0]), "r"((b)[1]))

__device__ __forceinline__ void cp16(uint32_t dst, const void* src, int src_sz) {
    asm volatile("cp.async.cg.shared.global [%0], [%1], 16, %2;"
                 :: "r"(dst), "l"(src), "r"(src_sz));
}
#define CP_COMMIT()  asm volatile("cp.async.commit_group;" ::: "memory")
#define CP_WAIT(N)   asm volatile("cp.async.wait_group %0;" :: "n"(N) : "memory")

// ---------------- fp32 -> (hi, lo) bf16 split ----------------
__global__ void cvt_split4(const float* __restrict__ X,
                           __nv_bfloat16* __restrict__ hi,
                           __nv_bfloat16* __restrict__ lo, int n4) {
    int i = blockIdx.x * blockDim.x + threadIdx.x;
    if (i >= n4) return;
    float4 x = ((const float4*)X)[i];
    __nv_bfloat16 h0 = __float2bfloat16(x.x), h1 = __float2bfloat16(x.y);
    __nv_bfloat16 h2 = __float2bfloat16(x.z), h3 = __float2bfloat16(x.w);
    __nv_bfloat16 l0 = __float2bfloat16(x.x - __bfloat162float(h0));
    __nv_bfloat16 l1 = __float2bfloat16(x.y - __bfloat162float(h1));
    __nv_bfloat16 l2 = __float2bfloat16(x.z - __bfloat162float(h2));
    __nv_bfloat16 l3 = __float2bfloat16(x.w - __bfloat162float(h3));
    __nv_bfloat162* H = reinterpret_cast<__nv_bfloat162*>(hi + 4 * (size_t)i);
    __nv_bfloat162* L = reinterpret_cast<__nv_bfloat162*>(lo + 4 * (size_t)i);
    H[0] = __halves2bfloat162(h0, h1); H[1] = __halves2bfloat162(h2, h3);
    L[0] = __halves2bfloat162(l0, l1); L[1] = __halves2bfloat162(l2, l3);
}

// build Bt[n][k] = W(k, n) split into hi/lo (fused Wq|Wk|Wv transpose)
__global__ void cvt_Bt(const float* __restrict__ Wq, const float* __restrict__ Wk,
                       const float* __restrict__ Wv) {
    int idx = blockIdx.x * blockDim.x + threadIdx.x;
    if (idx >= 384 * 128) return;
    int n = idx >> 7, k = idx & 127;
    float v;
    if (n < 128)      v = Wq[k * 128 + n];
    else if (n < 256) v = Wk[k * 128 + (n - 128)];
    else              v = Wv[k * 128 + (n - 256)];
    __nv_bfloat16 h = __float2bfloat16(v);
    g_Bthi[idx] = h;
    g_Btlo[idx] = __float2bfloat16(v - __bfloat162float(h));
}

__global__ void cvt_Wot(const float* __restrict__ Wo) {
    int idx = blockIdx.x * blockDim.x + threadIdx.x;
    if (idx >= 128 * 128) return;
    int n = idx >> 7, k = idx & 127;
    float v = Wo[k * 128 + n];
    __nv_bfloat16 h = __float2bfloat16(v);
    g_Wohi[idx] = h;
    g_Wolo[idx] = __float2bfloat16(v - __bfloat162float(h));
}

// ---------------- bias: fold query into q/k biases ----------------
__global__ void bias_kernel(const float* __restrict__ qe,
                            const float* __restrict__ Wq, const float* __restrict__ bq,
                            const float* __restrict__ Wk, const float* __restrict__ bk,
                            const float* __restrict__ bv) {
    __shared__ float qs[128];
    int j = threadIdx.x;
    qs[j] = qe[j];
    __syncthreads();
    int b = blockIdx.x;
    if (b == 0) {
        float c = bq[j];
        #pragma unroll 4
        for (int i = 0; i < 128; i++) c += qs[i] * Wq[(128 + i) * 128 + j];
        g_biasp[j] = c;
    } else if (b == 1) {
        float c = bk[j];
        #pragma unroll 4
        for (int i = 0; i < 128; i++) c += qs[i] * Wk[(128 + i) * 128 + j];
        g_biasp[128 + j] = c;
    } else {
        g_biasp[256 + j] = bv[j];
    }
}

// ---------------- HMMA split-bf16 GEMM, cp.async double-buffered ----------------
// C[M,Nout] 128x128 tile = (Ahi+Alo)[M,128] @ (Bhi+Blo)[Nout,128]^T + bias
// D = Ahi*Bhi + Ahi*Blo + Alo*Bhi, fp32 accumulators.
// 256 threads = 8 warps (4m x 2n), warp tile 32x64, m16n8k16.
#define SM_STRIDE  40
#define SM_TILE    (128 * SM_STRIDE)          // bf16 elems per tile
#define TILE_BYTES (SM_TILE * 2)              // 10240
#define BUF_BYTES  (4 * TILE_BYTES)           // 40960 per chunk buffer
#define GEMM_SMEM  (2 * BUF_BYTES)            // 81920

__global__ __launch_bounds__(256) void gemm_mma(
        const __nv_bfloat16* __restrict__ Ahi, const __nv_bfloat16* __restrict__ Alo,
        const __nv_bfloat16* __restrict__ Bhi, const __nv_bfloat16* __restrict__ Blo,
        const float* __restrict__ bias, float* __restrict__ C,
        int M, int Nout) {
    extern __shared__ __align__(16) char dsm[];
    __nv_bfloat16* sm = (__nv_bfloat16*)dsm;
    const int tid = threadIdx.x;
    const int wid = tid >> 5, lane = tid & 31;
    const int m0 = blockIdx.x * 128, n0 = blockIdx.y * 128;
    const int wm = (wid & 3) * 32;
    const int wn = (wid >> 2) * 64;
    const uint32_t smb = smem_u32(sm);

    float acc[2][8][4];
    #pragma unroll
    for (int i = 0; i < 2; i++)
        #pragma unroll
        for (int j = 0; j < 8; j++)
            #pragma unroll
            for (int c = 0; c < 4; c++) acc[i][j][c] = 0.f;

    const __nv_bfloat16* tileP[4] = {Ahi, Alo, Bhi, Blo};

    // stage one 32-wide k-chunk (4 tiles) into buffer `buf` via cp.async
    auto stage = [&](int kc, int buf) {
        #pragma unroll
        for (int t = 0; t < 4; t++) {
            const __nv_bfloat16* P = tileP[t];
            const int base_row = (t < 2) ? m0 : n0;
            const bool isA = (t < 2);
            #pragma unroll
            for (int it = 0; it < 2; it++) {
                int idx = tid + it * 256;          // 0..511
                int row = idx >> 2, c8 = idx & 3;  // 16B chunk within 32-elem row
                bool valid = (!isA) || (base_row + row < M);
                int r = valid ? row : 0;
                const void* src = P + (size_t)(base_row + r) * 128 + kc * 32 + c8 * 8;
                uint32_t dst = smb + buf * BUF_BYTES + t * TILE_BYTES
                             + 2 * (row * SM_STRIDE + c8 * 8);
                cp16(dst, src, valid ? 16 : 0);
            }
        }
        CP_COMMIT();
    };

    // ldmatrix lane address components
    const int a_row = lane & 15, a_c8 = (lane >> 4);
    const int b_row = (lane & 7) | ((lane >> 4) << 3);
    const int b_c8 = (lane >> 3) & 1;

    stage(0, 0);
    for (int kc = 0; kc < 4; kc++) {
        const int buf = kc & 1;
        if (kc + 1 < 4) {
            stage(kc + 1, buf ^ 1);
            CP_WAIT(1);
        } else {
            CP_WAIT(0);
        }
        __syncthreads();

        const uint32_t bb = smb + buf * BUF_BYTES;
        #pragma unroll
        for (int pass = 0; pass < 3; pass++) {
            const uint32_t tbA = (pass == 2) ? TILE_BYTES : 0;                      // Alo : Ahi
            const uint32_t tbB = (pass == 1) ? 3u * TILE_BYTES : 2u * TILE_BYTES;   // Blo : Bhi
            #pragma unroll
            for (int ks = 0; ks < 32; ks += 16) {
                uint32_t a[2][4], b[8][2];
                #pragma unroll
                for (int mi = 0; mi < 2; mi++) {
                    uint32_t addr = bb + tbA + 2 * ((wm + mi * 16 + a_row) * SM_STRIDE
                                                    + ks + a_c8 * 8);
                    LDSM_X4(a[mi][0], a[mi][1], a[mi][2], a[mi][3], addr);
                }
                #pragma unroll
                for (int nb = 0; nb < 4; nb++) {
                    uint32_t addr = bb + tbB + 2 * ((wn + nb * 16 + b_row) * SM_STRIDE
                                                    + ks + b_c8 * 8);
                    LDSM_X4(b[2 * nb][0], b[2 * nb][1], b[2 * nb + 1][0], b[2 * nb + 1][1], addr);
                }
                #pragma unroll
                for (int mi = 0; mi < 2; mi++)
                    #pragma unroll
                    for (int ni = 0; ni < 8; ni++)
                        MMA16816(acc[mi][ni], a[mi], b[ni]);
            }
        }
        __syncthreads();
    }

    // epilogue
    const int tq = lane >> 2, tr = lane & 3;
    #pragma unroll
    for (int ni = 0; ni < 8; ni++) {
        const int col = n0 + wn + ni * 8 + tr * 2;
        const float b0 = bias[col], b1 = bias[col + 1];
        #pragma unroll
        for (int mi = 0; mi < 2; mi++) {
            int mlow = m0 + wm + mi * 16 + tq;
            if (mlow < M) {
                float2 o = make_float2(acc[mi][ni][0] + b0, acc[mi][ni][1] + b1);
                *(float2*)(C + (size_t)mlow * Nout + col) = o;
            }
            int mhigh = mlow + 8;
            if (mhigh < M) {
                float2 o = make_float2(acc[mi][ni][2] + b0, acc[mi][ni][3] + b1);
                *(float2*)(C + (size_t)mhigh * Nout + col) = o;
            }
        }
    }
}

// ---------------- counting sort by dst ----------------
__global__ void hist_kernel(const int* __restrict__ dst) {
    int e = blockIdx.x * blockDim.x + threadIdx.x;
    if (e < N_EDGES) atomicAdd(&g_cnt[dst[e]], 1);
}

// block-level exclusive scan (1024 threads/block)
__global__ __launch_bounds__(1024) void scan1_kernel() {
    __shared__ int ws[32];
    const int t = threadIdx.x, lane = t & 31, wid = t >> 5;
    int i = blockIdx.x * 1024 + t;
    int v = (i < N_NODES) ? g_cnt[i] : 0;
    int x = v;
    #pragma unroll
    for (int d = 1; d < 32; d <<= 1) {
        int y = __shfl_up_sync(0xffffffffu, x, d);
        if (lane >= d) x += y;
    }
    if (lane == 31) ws[wid] = x;
    __syncthreads();
    if (wid == 0) {
        int s = ws[lane];
        #pragma unroll
        for (int d = 1; d < 32; d <<= 1) {
            int y = __shfl_up_sync(0xffffffffu, s, d);
            if (lane >= d) s += y;
        }
        ws[lane] = s;
    }
    __syncthreads();
    int excl = x - v + (wid > 0 ? ws[wid - 1] : 0);
    if (i < N_NODES) g_excl[i] = excl;
    if (t == 1023) g_bsum[blockIdx.x] = ws[31];
}

// scan of block sums (<=64 partials)
__global__ void scan2_kernel(int nb) {
    __shared__ int ws[2];
    const int t = threadIdx.x, lane = t & 31, wid = t >> 5;
    int v = (t < nb) ? g_bsum[t] : 0;
    int x = v;
    #pragma unroll
    for (int d = 1; d < 32; d <<= 1) {
        int y = __shfl_up_sync(0xffffffffu, x, d);
        if (lane >= d) x += y;
    }
    if (lane == 31) ws[wid] = x;
    __syncthreads();
    if (wid == 1) x += ws[0];
    g_boff[t] = x - v;
}

__global__ __launch_bounds__(1024) void scan3_kernel() {
    int i = blockIdx.x * 1024 + threadIdx.x;
    if (i < N_NODES) {
        int s = g_excl[i] + g_boff[blockIdx.x];
        g_start[i] = s;
        g_fill[i] = s;
    }
    if (i == 0) g_start[N_NODES] = N_EDGES;
}

__global__ void scatter_kernel(const int* __restrict__ src,
                               const int* __restrict__ dst,
                               const int* __restrict__ typ) {
    int e = blockIdx.x * blockDim.x + threadIdx.x;
    if (e >= N_EDGES) return;
    int d = dst[e];
    int pos = atomicAdd(&g_fill[d], 1);
    g_sorted[pos] = make_int2(src[e], typ[e]);
}

// ---------------- warp-per-dst softmax aggregation ----------------
// rel table staged in smem; output written directly as split bf16 (AOhi/AOlo).
__global__ void agg_kernel(const float* __restrict__ rel) {
    __shared__ float srel[N_REL * 128];
    const int tid = threadIdx.x, wid = tid >> 5, lane = tid & 31;
    for (int i = tid; i < N_REL * 32; i += 256)
        ((float4*)srel)[i] = ((const float4*)rel)[i];
    __syncthreads();

    const float4* __restrict__ QKV4 = (const float4*)g_QKV;  // stride 96 float4/node

    for (int dst = blockIdx.x * 8 + wid; dst < N_NODES; dst += 8 * gridDim.x) {
        float4 qv = QKV4[(size_t)dst * 96 + lane];
        int beg = g_start[dst], end = g_start[dst + 1];

        float4 acc = make_float4(0.f, 0.f, 0.f, 0.f);
        float sacc = 0.f;

        for (int e0 = beg; e0 < end; e0 += 32) {
            int2 er = make_int2(0, 0);
            if (e0 + lane < end) er = g_sorted[e0 + lane];
            int cnt = min(32, end - e0);
            for (int i = 0; i < cnt; i++) {
                int src = __shfl_sync(0xffffffffu, er.x, i);
                int typ = __shfl_sync(0xffffffffu, er.y, i);
                float4 kv = QKV4[(size_t)src * 96 + 32 + lane];
                float4 vv = QKV4[(size_t)src * 96 + 64 + lane];
                float4 rb = *(const float4*)&srel[typ * 128 + lane * 4];
                float p = qv.x * (kv.x + rb.x) + qv.y * (kv.y + rb.y)
                        + qv.z * (kv.z + rb.z) + qv.w * (kv.w + rb.w);
                p += __shfl_xor_sync(0xffffffffu, p, 1);
                p += __shfl_xor_sync(0xffffffffu, p, 2);
                float w = __expf(p * 0.25f);
                sacc += w;
                acc.x += w * vv.x; acc.y += w * vv.y;
                acc.z += w * vv.z; acc.w += w * vv.w;
            }
        }
        float inv = 1.0f / (sacc + 1e-8f);
        float4 o = make_float4(acc.x * inv, acc.y * inv, acc.z * inv, acc.w * inv);
        // write split bf16 directly
        __nv_bfloat16 h0 = __float2bfloat16(o.x), h1 = __float2bfloat16(o.y);
        __nv_bfloat16 h2 = __float2bfloat16(o.z), h3 = __float2bfloat16(o.w);
        __nv_bfloat16 l0 = __float2bfloat16(o.x - __bfloat162float(h0));
        __nv_bfloat16 l1 = __float2bfloat16(o.y - __bfloat162float(h1));
        __nv_bfloat16 l2 = __float2bfloat16(o.z - __bfloat162float(h2));
        __nv_bfloat16 l3 = __float2bfloat16(o.w - __bfloat162float(h3));
        __nv_bfloat162* H = (__nv_bfloat162*)(g_AOhi + (size_t)dst * 128 + lane * 4);
        __nv_bfloat162* L = (__nv_bfloat162*)(g_AOlo + (size_t)dst * 128 + lane * 4);
        H[0] = __halves2bfloat162(h0, h1); H[1] = __halves2bfloat162(h2, h3);
        L[0] = __halves2bfloat162(l0, l1); L[1] = __halves2bfloat162(l2, l3);
    }
}

// ---------------- launch ----------------
extern "C" void kernel_launch(void* const* d_in, const int* in_sizes, int n_in,
                              void* d_out, int out_size) {
    const float* node_features = (const float*)d_in[0];
    const float* query_emb     = (const float*)d_in[1];
    const float* rel_emb       = (const float*)d_in[2];
    const float* Wq            = (const float*)d_in[3];
    const float* bq            = (const float*)d_in[4];
    const float* Wk            = (const float*)d_in[5];
    const float* bk            = (const float*)d_in[6];
    const float* Wv            = (const float*)d_in[7];
    const float* bv            = (const float*)d_in[8];
    const float* Wo            = (const float*)d_in[9];
    const float* bo            = (const float*)d_in[10];
    const int*   edge_index    = (const int*)d_in[11];
    const int*   edge_type     = (const int*)d_in[12];
    float* out = (float*)d_out;

    const int* e_src = edge_index;
    const int* e_dst = edge_index + N_EDGES;

    float* d_QKV;  cudaGetSymbolAddress((void**)&d_QKV,  g_QKV);
    float* d_bp;   cudaGetSymbolAddress((void**)&d_bp,   g_biasp);
    int*   d_cnt;  cudaGetSymbolAddress((void**)&d_cnt,  g_cnt);
    __nv_bfloat16 *d_Ahi, *d_Alo, *d_AOhi, *d_AOlo, *d_Bthi, *d_Btlo, *d_Wohi, *d_Wolo;
    cudaGetSymbolAddress((void**)&d_Ahi,  g_Ahi);
    cudaGetSymbolAddress((void**)&d_Alo,  g_Alo);
    cudaGetSymbolAddress((void**)&d_AOhi, g_AOhi);
    cudaGetSymbolAddress((void**)&d_AOlo, g_AOlo);
    cudaGetSymbolAddress((void**)&d_Bthi, g_Bthi);
    cudaGetSymbolAddress((void**)&d_Btlo, g_Btlo);
    cudaGetSymbolAddress((void**)&d_Wohi, g_Wohi);
    cudaGetSymbolAddress((void**)&d_Wolo, g_Wolo);

    static bool attr_set = false;
    if (!attr_set) {
        cudaFuncSetAttribute(gemm_mma, cudaFuncAttributeMaxDynamicSharedMemorySize,
                             GEMM_SMEM);
        attr_set = true;
    }

    // prep: weight transposes + splits, bias fold, edge sort
    cvt_Bt<<<(384 * 128 + 255) / 256, 256>>>(Wq, Wk, Wv);
    cvt_Wot<<<(128 * 128 + 255) / 256, 256>>>(Wo);
    bias_kernel<<<3, 128>>>(query_emb, Wq, bq, Wk, bk, bv);
    cudaMemsetAsync(d_cnt, 0, N_NODES * sizeof(int));
    cvt_split4<<<(N_NODES * 128 / 4 + 255) / 256, 256>>>(node_features, d_Ahi, d_Alo,
                                                         N_NODES * 128 / 4);

    // fused QKV projection: 50000 x 384 (HMMA split-bf16, cp.async pipelined)
    {
        dim3 grid((N_NODES + 127) / 128, 3);
        gemm_mma<<<grid, 256, GEMM_SMEM>>>(d_Ahi, d_Alo, d_Bthi, d_Btlo, d_bp, d_QKV,
                                           N_NODES, 384);
    }

    const int NB = (N_NODES + 1023) / 1024;  // 49
    hist_kernel<<<(N_EDGES + 255) / 256, 256>>>(e_dst);
    scan1_kernel<<<NB, 1024>>>();
    scan2_kernel<<<1, 64>>>(NB);
    scan3_kernel<<<NB, 1024>>>();
    scatter_kernel<<<(N_EDGES + 255) / 256, 256>>>(e_src, e_dst, edge_type);

    agg_kernel<<<1024, 256>>>(rel_emb);

    // output projection: 50000 x 128 (HMMA split-bf16)
    {
        dim3 grid((N_NODES + 127) / 128, 1);
        gemm_mma<<<grid, 256, GEMM_SMEM>>>(d_AOhi, d_AOlo, d_Wohi, d_Wolo, bo, out,
                                           N_NODES, 128);
    }
}

// round 14
// speedup vs baseline: 1.8713x; 1.0643x over previous
#include <cuda_runtime.h>
#include <cuda_bf16.h>
#include <cuda_fp16.h>
#include <math.h>
#include <stdint.h>

#define N_NODES 50000
#define N_EDGES 800000
#define HIDDEN  128
#define N_REL   64

// ---------------- device scratch ----------------
__device__ float  g_Qf[N_NODES * 128];           // q per node, fp32
__device__ __half g_KV16[N_NODES * 256];         // per node: k[128] | v[128], fp16
__device__ float  g_biasp[384];                  // [cq | ck | bv]
__device__ int    g_cnt[N_NODES];
__device__ int    g_excl[N_NODES];
__device__ int    g_bsum[64];
__device__ int    g_boff[64];
__device__ int    g_start[N_NODES + 1];
__device__ int    g_fill[N_NODES];
__device__ int2   g_sorted[N_EDGES];             // (src, type) sorted by dst
// split-precision bf16 operands
__device__ __nv_bfloat16 g_Ahi[N_NODES * 128];
__device__ __nv_bfloat16 g_Alo[N_NODES * 128];
__device__ __nv_bfloat16 g_AOhi[N_NODES * 128];
__device__ __nv_bfloat16 g_AOlo[N_NODES * 128];
__device__ __nv_bfloat16 g_Bthi[384 * 128];      // QKV weights, [n][k] K-major
__device__ __nv_bfloat16 g_Btlo[384 * 128];
__device__ __nv_bfloat16 g_Wohi[128 * 128];      // Wo^T, [n][k] K-major
__device__ __nv_bfloat16 g_Wolo[128 * 128];

// ---------------- PTX helpers (baseline ISA only) ----------------
__device__ __forceinline__ uint32_t smem_u32(const void* p) {
    uint32_t a;
    asm("{ .reg .u64 t; cvta.to.shared.u64 t, %1; cvt.u32.u64 %0, t; }" : "=r"(a) : "l"(p));
    return a;
}

#define LDSM_X4(r0, r1, r2, r3, addr)                                              \
    asm volatile("ldmatrix.sync.aligned.m8n8.x4.shared.b16 {%0,%1,%2,%3}, [%4];"   \
                 : "=r"(r0), "=r"(r1), "=r"(r2), "=r"(r3) : "r"(addr))

#define MMA16816(c, a, b)                                                          \
    asm volatile("mma.sync.aligned.m16n8k16.row.col.f32.bf16.bf16.f32 "            \
                 "{%0,%1,%2,%3},{%4,%5,%6,%7},{%8,%9},{%0,%1,%2,%3};"              \
                 : "+f"((c)[0]), "+f"((c)[1]), "+f"((c)[2]), "+f"((c)[3])          \
                 : "r"((a)[0]), "r"((a)[1]), "r"((a)[2]), "r"((a)[3]),             \
                   "r"((b)[0]), "r"((b)[1]))

__device__ __forceinline__ void cp16(uint32_t dst, const void* src, int src_sz) {
    asm volatile("cp.async.cg.shared.global [%0], [%1], 16, %2;"
                 :: "r"(dst), "l"(src), "r"(src_sz));
}
#define CP_COMMIT()  asm volatile("cp.async.commit_group;" ::: "memory")
#define CP_WAIT(N)   asm volatile("cp.async.wait_group %0;" :: "n"(N) : "memory")

// ---------------- fp32 -> (hi, lo) bf16 split ----------------
__global__ void cvt_split4(const float* __restrict__ X,
                           __nv_bfloat16* __restrict__ hi,
                           __nv_bfloat16* __restrict__ lo, int n4) {
    int i = blockIdx.x * blockDim.x + threadIdx.x;
    if (i >= n4) return;
    float4 x = ((const float4*)X)[i];
    __nv_bfloat16 h0 = __float2bfloat16(x.x), h1 = __float2bfloat16(x.y);
    __nv_bfloat16 h2 = __float2bfloat16(x.z), h3 = __float2bfloat16(x.w);
    __nv_bfloat16 l0 = __float2bfloat16(x.x - __bfloat162float(h0));
    __nv_bfloat16 l1 = __float2bfloat16(x.y - __bfloat162float(h1));
    __nv_bfloat16 l2 = __float2bfloat16(x.z - __bfloat162float(h2));
    __nv_bfloat16 l3 = __float2bfloat16(x.w - __bfloat162float(h3));
    __nv_bfloat162* H = reinterpret_cast<__nv_bfloat162*>(hi + 4 * (size_t)i);
    __nv_bfloat162* L = reinterpret_cast<__nv_bfloat162*>(lo + 4 * (size_t)i);
    H[0] = __halves2bfloat162(h0, h1); H[1] = __halves2bfloat162(h2, h3);
    L[0] = __halves2bfloat162(l0, l1); L[1] = __halves2bfloat162(l2, l3);
}

// build Bt[n][k] = W(k, n) split into hi/lo (fused Wq|Wk|Wv transpose)
__global__ void cvt_Bt(const float* __restrict__ Wq, const float* __restrict__ Wk,
                       const float* __restrict__ Wv) {
    int idx = blockIdx.x * blockDim.x + threadIdx.x;
    if (idx >= 384 * 128) return;
    int n = idx >> 7, k = idx & 127;
    float v;
    if (n < 128)      v = Wq[k * 128 + n];
    else if (n < 256) v = Wk[k * 128 + (n - 128)];
    else              v = Wv[k * 128 + (n - 256)];
    __nv_bfloat16 h = __float2bfloat16(v);
    g_Bthi[idx] = h;
    g_Btlo[idx] = __float2bfloat16(v - __bfloat162float(h));
}

__global__ void cvt_Wot(const float* __restrict__ Wo) {
    int idx = blockIdx.x * blockDim.x + threadIdx.x;
    if (idx >= 128 * 128) return;
    int n = idx >> 7, k = idx & 127;
    float v = Wo[k * 128 + n];
    __nv_bfloat16 h = __float2bfloat16(v);
    g_Wohi[idx] = h;
    g_Wolo[idx] = __float2bfloat16(v - __bfloat162float(h));
}

// ---------------- bias: fold query into q/k biases ----------------
__global__ void bias_kernel(const float* __restrict__ qe,
                            const float* __restrict__ Wq, const float* __restrict__ bq,
                            const float* __restrict__ Wk, const float* __restrict__ bk,
                            const float* __restrict__ bv) {
    __shared__ float qs[128];
    int j = threadIdx.x;
    qs[j] = qe[j];
    __syncthreads();
    int b = blockIdx.x;
    if (b == 0) {
        float c = bq[j];
        #pragma unroll 4
        for (int i = 0; i < 128; i++) c += qs[i] * Wq[(128 + i) * 128 + j];
        g_biasp[j] = c;
    } else if (b == 1) {
        float c = bk[j];
        #pragma unroll 4
        for (int i = 0; i < 128; i++) c += qs[i] * Wk[(128 + i) * 128 + j];
        g_biasp[128 + j] = c;
    } else {
        g_biasp[256 + j] = bv[j];
    }
}

// ---------------- HMMA split-bf16 GEMM, cp.async double-buffered ----------------
// D = Ahi*Bhi + Ahi*Blo + Alo*Bhi, fp32 accumulators.
// 256 threads = 8 warps (4m x 2n), warp tile 32x64, m16n8k16.
// qkv mode: blockIdx.y==0 -> fp32 into C (stride Cstride); y==1/2 -> fp16 into
// KV16 per-node record [k|v] at half-offset (y-1)*128.
#define SM_STRIDE  40
#define SM_TILE    (128 * SM_STRIDE)
#define TILE_BYTES (SM_TILE * 2)
#define BUF_BYTES  (4 * TILE_BYTES)
#define GEMM_SMEM  (2 * BUF_BYTES)

__global__ __launch_bounds__(256) void gemm_mma(
        const __nv_bfloat16* __restrict__ Ahi, const __nv_bfloat16* __restrict__ Alo,
        const __nv_bfloat16* __restrict__ Bhi, const __nv_bfloat16* __restrict__ Blo,
        const float* __restrict__ bias, float* __restrict__ C, int Cstride,
        __half* __restrict__ KV16, int qkv, int M) {
    extern __shared__ __align__(16) char dsm[];
    __nv_bfloat16* sm = (__nv_bfloat16*)dsm;
    const int tid = threadIdx.x;
    const int wid = tid >> 5, lane = tid & 31;
    const int m0 = blockIdx.x * 128, n0 = blockIdx.y * 128;
    const int wm = (wid & 3) * 32;
    const int wn = (wid >> 2) * 64;
    const uint32_t smb = smem_u32(sm);

    float acc[2][8][4];
    #pragma unroll
    for (int i = 0; i < 2; i++)
        #pragma unroll
        for (int j = 0; j < 8; j++)
            #pragma unroll
            for (int c = 0; c < 4; c++) acc[i][j][c] = 0.f;

    const __nv_bfloat16* tileP[4] = {Ahi, Alo, Bhi, Blo};

    auto stage = [&](int kc, int buf) {
        #pragma unroll
        for (int t = 0; t < 4; t++) {
            const __nv_bfloat16* P = tileP[t];
            const int base_row = (t < 2) ? m0 : n0;
            const bool isA = (t < 2);
            #pragma unroll
            for (int it = 0; it < 2; it++) {
                int idx = tid + it * 256;
                int row = idx >> 2, c8 = idx & 3;
                bool valid = (!isA) || (base_row + row < M);
                int r = valid ? row : 0;
                const void* src = P + (size_t)(base_row + r) * 128 + kc * 32 + c8 * 8;
                uint32_t dst = smb + buf * BUF_BYTES + t * TILE_BYTES
                             + 2 * (row * SM_STRIDE + c8 * 8);
                cp16(dst, src, valid ? 16 : 0);
            }
        }
        CP_COMMIT();
    };

    const int a_row = lane & 15, a_c8 = (lane >> 4);
    const int b_row = (lane & 7) | ((lane >> 4) << 3);
    const int b_c8 = (lane >> 3) & 1;

    stage(0, 0);
    for (int kc = 0; kc < 4; kc++) {
        const int buf = kc & 1;
        if (kc + 1 < 4) {
            stage(kc + 1, buf ^ 1);
            CP_WAIT(1);
        } else {
            CP_WAIT(0);
        }
        __syncthreads();

        const uint32_t bb = smb + buf * BUF_BYTES;
        #pragma unroll
        for (int pass = 0; pass < 3; pass++) {
            const uint32_t tbA = (pass == 2) ? TILE_BYTES : 0;
            const uint32_t tbB = (pass == 1) ? 3u * TILE_BYTES : 2u * TILE_BYTES;
            #pragma unroll
            for (int ks = 0; ks < 32; ks += 16) {
                uint32_t a[2][4], b[8][2];
                #pragma unroll
                for (int mi = 0; mi < 2; mi++) {
                    uint32_t addr = bb + tbA + 2 * ((wm + mi * 16 + a_row) * SM_STRIDE
                                                    + ks + a_c8 * 8);
                    LDSM_X4(a[mi][0], a[mi][1], a[mi][2], a[mi][3], addr);
                }
                #pragma unroll
                for (int nb = 0; nb < 4; nb++) {
                    uint32_t addr = bb + tbB + 2 * ((wn + nb * 16 + b_row) * SM_STRIDE
                                                    + ks + b_c8 * 8);
                    LDSM_X4(b[2 * nb][0], b[2 * nb][1], b[2 * nb + 1][0], b[2 * nb + 1][1], addr);
                }
                #pragma unroll
                for (int mi = 0; mi < 2; mi++)
                    #pragma unroll
                    for (int ni = 0; ni < 8; ni++)
                        MMA16816(acc[mi][ni], a[mi], b[ni]);
            }
        }
        __syncthreads();
    }

    // epilogue
    const int tq = lane >> 2, tr = lane & 3;
    const bool fp16out = (qkv && blockIdx.y > 0);
    const int hbase = (blockIdx.y == 1) ? 0 : 128;  // k-half or v-half
    #pragma unroll
    for (int ni = 0; ni < 8; ni++) {
        const int col = n0 + wn + ni * 8 + tr * 2;
        const float b0 = bias[col], b1 = bias[col + 1];
        #pragma unroll
        for (int mi = 0; mi < 2; mi++) {
            int mlow = m0 + wm + mi * 16 + tq;
            int mhigh = mlow + 8;
            if (fp16out) {
                int lc = col - n0;
                if (mlow < M) {
                    __half2 h = __float22half2_rn(
                        make_float2(acc[mi][ni][0] + b0, acc[mi][ni][1] + b1));
                    *(__half2*)(KV16 + (size_t)mlow * 256 + hbase + lc) = h;
                }
                if (mhigh < M) {
                    __half2 h = __float22half2_rn(
                        make_float2(acc[mi][ni][2] + b0, acc[mi][ni][3] + b1));
                    *(__half2*)(KV16 + (size_t)mhigh * 256 + hbase + lc) = h;
                }
            } else {
                if (mlow < M) {
                    float2 o = make_float2(acc[mi][ni][0] + b0, acc[mi][ni][1] + b1);
                    *(float2*)(C + (size_t)mlow * Cstride + col) = o;
                }
                if (mhigh < M) {
                    float2 o = make_float2(acc[mi][ni][2] + b0, acc[mi][ni][3] + b1);
                    *(float2*)(C + (size_t)mhigh * Cstride + col) = o;
                }
            }
        }
    }
}

// ---------------- counting sort by dst ----------------
__global__ void hist_kernel(const int* __restrict__ dst) {
    int e = blockIdx.x * blockDim.x + threadIdx.x;
    if (e < N_EDGES) atomicAdd(&g_cnt[dst[e]], 1);
}

__global__ __launch_bounds__(1024) void scan1_kernel() {
    __shared__ int ws[32];
    const int t = threadIdx.x, lane = t & 31, wid = t >> 5;
    int i = blockIdx.x * 1024 + t;
    int v = (i < N_NODES) ? g_cnt[i] : 0;
    int x = v;
    #pragma unroll
    for (int d = 1; d < 32; d <<= 1) {
        int y = __shfl_up_sync(0xffffffffu, x, d);
        if (lane >= d) x += y;
    }
    if (lane == 31) ws[wid] = x;
    __syncthreads();
    if (wid == 0) {
        int s = ws[lane];
        #pragma unroll
        for (int d = 1; d < 32; d <<= 1) {
            int y = __shfl_up_sync(0xffffffffu, s, d);
            if (lane >= d) s += y;
        }
        ws[lane] = s;
    }
    __syncthreads();
    int excl = x - v + (wid > 0 ? ws[wid - 1] : 0);
    if (i < N_NODES) g_excl[i] = excl;
    if (t == 1023) g_bsum[blockIdx.x] = ws[31];
}

__global__ void scan2_kernel(int nb) {
    __shared__ int ws[2];
    const int t = threadIdx.x, lane = t & 31, wid = t >> 5;
    int v = (t < nb) ? g_bsum[t] : 0;
    int x = v;
    #pragma unroll
    for (int d = 1; d < 32; d <<= 1) {
        int y = __shfl_up_sync(0xffffffffu, x, d);
        if (lane >= d) x += y;
    }
    if (lane == 31) ws[wid] = x;
    __syncthreads();
    if (wid == 1) x += ws[0];
    g_boff[t] = x - v;
}

__global__ __launch_bounds__(1024) void scan3_kernel() {
    int i = blockIdx.x * 1024 + threadIdx.x;
    if (i < N_NODES) {
        int s = g_excl[i] + g_boff[blockIdx.x];
        g_start[i] = s;
        g_fill[i] = s;
    }
    if (i == 0) g_start[N_NODES] = N_EDGES;
}

__global__ void scatter_kernel(const int* __restrict__ src,
                               const int* __restrict__ dst,
                               const int* __restrict__ typ) {
    int e = blockIdx.x * blockDim.x + threadIdx.x;
    if (e >= N_EDGES) return;
    int d = dst[e];
    int pos = atomicAdd(&g_fill[d], 1);
    g_sorted[pos] = make_int2(src[e], typ[e]);
}

// ---------------- warp-per-dst softmax aggregation (fp16 k/v gather) ----------------
__global__ void agg_kernel(const float* __restrict__ rel) {
    __shared__ float srel[N_REL * 128];
    const int tid = threadIdx.x, wid = tid >> 5, lane = tid & 31;
    for (int i = tid; i < N_REL * 32; i += 256)
        ((float4*)srel)[i] = ((const float4*)rel)[i];
    __syncthreads();

    for (int dst = blockIdx.x * 8 + wid; dst < N_NODES; dst += 8 * gridDim.x) {
        float4 qv = *(const float4*)(g_Qf + (size_t)dst * 128 + lane * 4);
        int beg = g_start[dst], end = g_start[dst + 1];

        float4 acc = make_float4(0.f, 0.f, 0.f, 0.f);
        float sacc = 0.f;

        for (int e0 = beg; e0 < end; e0 += 32) {
            int2 er = make_int2(0, 0);
            if (e0 + lane < end) er = g_sorted[e0 + lane];
            int cnt = min(32, end - e0);
            for (int i = 0; i < cnt; i++) {
                int src = __shfl_sync(0xffffffffu, er.x, i);
                int typ = __shfl_sync(0xffffffffu, er.y, i);
                uint2 kraw = *(const uint2*)(g_KV16 + (size_t)src * 256 + lane * 4);
                uint2 vraw = *(const uint2*)(g_KV16 + (size_t)src * 256 + 128 + lane * 4);
                float4 rb = *(const float4*)&srel[typ * 128 + lane * 4];
                float2 k01 = __half22float2(*(__half2*)&kraw.x);
                float2 k23 = __half22float2(*(__half2*)&kraw.y);
                float p = qv.x * (k01.x + rb.x) + qv.y * (k01.y + rb.y)
                        + qv.z * (k23.x + rb.z) + qv.w * (k23.y + rb.w);
                p += __shfl_xor_sync(0xffffffffu, p, 1);
                p += __shfl_xor_sync(0xffffffffu, p, 2);
                float w = __expf(p * 0.25f);
                float2 v01 = __half22float2(*(__half2*)&vraw.x);
                float2 v23 = __half22float2(*(__half2*)&vraw.y);
                sacc += w;
                acc.x += w * v01.x; acc.y += w * v01.y;
                acc.z += w * v23.x; acc.w += w * v23.y;
            }
        }
        float inv = 1.0f / (sacc + 1e-8f);
        float4 o = make_float4(acc.x * inv, acc.y * inv, acc.z * inv, acc.w * inv);
        __nv_bfloat16 h0 = __float2bfloat16(o.x), h1 = __float2bfloat16(o.y);
        __nv_bfloat16 h2 = __float2bfloat16(o.z), h3 = __float2bfloat16(o.w);
        __nv_bfloat16 l0 = __float2bfloat16(o.x - __bfloat162float(h0));
        __nv_bfloat16 l1 = __float2bfloat16(o.y - __bfloat162float(h1));
        __nv_bfloat16 l2 = __float2bfloat16(o.z - __bfloat162float(h2));
        __nv_bfloat16 l3 = __float2bfloat16(o.w - __bfloat162float(h3));
        __nv_bfloat162* H = (__nv_bfloat162*)(g_AOhi + (size_t)dst * 128 + lane * 4);
        __nv_bfloat162* L = (__nv_bfloat162*)(g_AOlo + (size_t)dst * 128 + lane * 4);
        H[0] = __halves2bfloat162(h0, h1); H[1] = __halves2bfloat162(h2, h3);
        L[0] = __halves2bfloat162(l0, l1); L[1] = __halves2bfloat162(l2, l3);
    }
}

// ---------------- launch ----------------
extern "C" void kernel_launch(void* const* d_in, const int* in_sizes, int n_in,
                              void* d_out, int out_size) {
    const float* node_features = (const float*)d_in[0];
    const float* query_emb     = (const float*)d_in[1];
    const float* rel_emb       = (const float*)d_in[2];
    const float* Wq            = (const float*)d_in[3];
    const float* bq            = (const float*)d_in[4];
    const float* Wk            = (const float*)d_in[5];
    const float* bk            = (const float*)d_in[6];
    const float* Wv            = (const float*)d_in[7];
    const float* bv            = (const float*)d_in[8];
    const float* Wo            = (const float*)d_in[9];
    const float* bo            = (const float*)d_in[10];
    const int*   edge_index    = (const int*)d_in[11];
    const int*   edge_type     = (const int*)d_in[12];
    float* out = (float*)d_out;

    const int* e_src = edge_index;
    const int* e_dst = edge_index + N_EDGES;

    float*  d_Qf;   cudaGetSymbolAddress((void**)&d_Qf,   g_Qf);
    __half* d_KV16; cudaGetSymbolAddress((void**)&d_KV16, g_KV16);
    float*  d_bp;   cudaGetSymbolAddress((void**)&d_bp,   g_biasp);
    int*    d_cnt;  cudaGetSymbolAddress((void**)&d_cnt,  g_cnt);
    __nv_bfloat16 *d_Ahi, *d_Alo, *d_AOhi, *d_AOlo, *d_Bthi, *d_Btlo, *d_Wohi, *d_Wolo;
    cudaGetSymbolAddress((void**)&d_Ahi,  g_Ahi);
    cudaGetSymbolAddress((void**)&d_Alo,  g_Alo);
    cudaGetSymbolAddress((void**)&d_AOhi, g_AOhi);
    cudaGetSymbolAddress((void**)&d_AOlo, g_AOlo);
    cudaGetSymbolAddress((void**)&d_Bthi, g_Bthi);
    cudaGetSymbolAddress((void**)&d_Btlo, g_Btlo);
    cudaGetSymbolAddress((void**)&d_Wohi, g_Wohi);
    cudaGetSymbolAddress((void**)&d_Wolo, g_Wolo);

    static bool attr_set = false;
    if (!attr_set) {
        cudaFuncSetAttribute(gemm_mma, cudaFuncAttributeMaxDynamicSharedMemorySize,
                             GEMM_SMEM);
        attr_set = true;
    }

    // prep
    cvt_Bt<<<(384 * 128 + 255) / 256, 256>>>(Wq, Wk, Wv);
    cvt_Wot<<<(128 * 128 + 255) / 256, 256>>>(Wo);
    bias_kernel<<<3, 128>>>(query_emb, Wq, bq, Wk, bk, bv);
    cudaMemsetAsync(d_cnt, 0, N_NODES * sizeof(int));
    cvt_split4<<<(N_NODES * 128 / 4 + 255) / 256, 256>>>(node_features, d_Ahi, d_Alo,
                                                         N_NODES * 128 / 4);

    // fused QKV projection: q -> fp32, k/v -> fp16 packed per node
    {
        dim3 grid((N_NODES + 127) / 128, 3);
        gemm_mma<<<grid, 256, GEMM_SMEM>>>(d_Ahi, d_Alo, d_Bthi, d_Btlo, d_bp,
                                           d_Qf, 128, d_KV16, 1, N_NODES);
    }

    const int NB = (N_NODES + 1023) / 1024;  // 49
    hist_kernel<<<(N_EDGES + 255) / 256, 256>>>(e_dst);
    scan1_kernel<<<NB, 1024>>>();
    scan2_kernel<<<1, 64>>>(NB);
    scan3_kernel<<<NB, 1024>>>();
    scatter_kernel<<<(N_EDGES + 255) / 256, 256>>>(e_src, e_dst, edge_type);

    agg_kernel<<<1024, 256>>>(rel_emb);

    // output projection: 50000 x 128 (HMMA split-bf16, fp32 out)
    {
        dim3 grid((N_NODES + 127) / 128, 1);
        gemm_mma<<<grid, 256, GEMM_SMEM>>>(d_AOhi, d_AOlo, d_Wohi, d_Wolo, bo,
                                           out, 128, (__half*)nullptr, 0, N_NODES);
    }
}

// round 17
// speedup vs baseline: 1.9592x; 1.0470x over previous
#include <cuda_runtime.h>
#include <cuda_bf16.h>
#include <cuda_fp16.h>
#include <math.h>
#include <stdint.h>

#define N_NODES 50000
#define N_EDGES 800000
#define HIDDEN  128
#define N_REL   64

// ---------------- device scratch ----------------
__device__ float  g_Qf[N_NODES * 128];           // q per node, fp32
__device__ __half g_KV16[N_NODES * 256];         // per node: k[128] | v[128], fp16
__device__ float  g_biasp[384];                  // [cq | ck | bv]
__device__ int    g_cnt[N_NODES];
__device__ int    g_excl[N_NODES];
__device__ int    g_bsum[64];
__device__ int    g_boff[64];
__device__ int    g_start[N_NODES + 1];
__device__ int    g_fill[N_NODES];
__device__ int2   g_sorted[N_EDGES];             // (src, type) sorted by dst
// split-precision bf16 operands
__device__ __nv_bfloat16 g_Ahi[N_NODES * 128];
__device__ __nv_bfloat16 g_Alo[N_NODES * 128];
__device__ __nv_bfloat16 g_AOhi[N_NODES * 128];
__device__ __nv_bfloat16 g_AOlo[N_NODES * 128];
__device__ __nv_bfloat16 g_Bthi[384 * 128];      // QKV weights, [n][k] K-major
__device__ __nv_bfloat16 g_Btlo[384 * 128];
__device__ __nv_bfloat16 g_Wohi[128 * 128];      // Wo^T, [n][k] K-major
__device__ __nv_bfloat16 g_Wolo[128 * 128];

// ---------------- PTX helpers (baseline ISA only) ----------------
__device__ __forceinline__ uint32_t smem_u32(const void* p) {
    uint32_t a;
    asm("{ .reg .u64 t; cvta.to.shared.u64 t, %1; cvt.u32.u64 %0, t; }" : "=r"(a) : "l"(p));
    return a;
}

#define LDSM_X4(r0, r1, r2, r3, addr)                                              \
    asm volatile("ldmatrix.sync.aligned.m8n8.x4.shared.b16 {%0,%1,%2,%3}, [%4];"   \
                 : "=r"(r0), "=r"(r1), "=r"(r2), "=r"(r3) : "r"(addr))

#define MMA16816(c, a, b)                                                          \
    asm volatile("mma.sync.aligned.m16n8k16.row.col.f32.bf16.bf16.f32 "            \
                 "{%0,%1,%2,%3},{%4,%5,%6,%7},{%8,%9},{%0,%1,%2,%3};"              \
                 : "+f"((c)[0]), "+f"((c)[1]), "+f"((c)[2]), "+f"((c)[3])          \
                 : "r"((a)[0]), "r"((a)[1]), "r"((a)[2]), "r"((a)[3]),             \
                   "r"((b)[0]), "r"((b)[1]))

__device__ __forceinline__ void cp16(uint32_t dst, const void* src, int src_sz) {
    asm volatile("cp.async.cg.shared.global [%0], [%1], 16, %2;"
                 :: "r"(dst), "l"(src), "r"(src_sz));
}
#define CP_COMMIT()  asm volatile("cp.async.commit_group;" ::: "memory")
#define CP_WAIT(N)   asm volatile("cp.async.wait_group %0;" :: "n"(N) : "memory")

// ---------------- fp32 -> (hi, lo) bf16 split ----------------
__global__ void cvt_split4(const float* __restrict__ X,
                           __nv_bfloat16* __restrict__ hi,
                           __nv_bfloat16* __restrict__ lo, int n4) {
    int i = blockIdx.x * blockDim.x + threadIdx.x;
    if (i >= n4) return;
    float4 x = ((const float4*)X)[i];
    __nv_bfloat16 h0 = __float2bfloat16(x.x), h1 = __float2bfloat16(x.y);
    __nv_bfloat16 h2 = __float2bfloat16(x.z), h3 = __float2bfloat16(x.w);
    __nv_bfloat16 l0 = __float2bfloat16(x.x - __bfloat162float(h0));
    __nv_bfloat16 l1 = __float2bfloat16(x.y - __bfloat162float(h1));
    __nv_bfloat16 l2 = __float2bfloat16(x.z - __bfloat162float(h2));
    __nv_bfloat16 l3 = __float2bfloat16(x.w - __bfloat162float(h3));
    __nv_bfloat162* H = reinterpret_cast<__nv_bfloat162*>(hi + 4 * (size_t)i);
    __nv_bfloat162* L = reinterpret_cast<__nv_bfloat162*>(lo + 4 * (size_t)i);
    H[0] = __halves2bfloat162(h0, h1); H[1] = __halves2bfloat162(h2, h3);
    L[0] = __halves2bfloat162(l0, l1); L[1] = __halves2bfloat162(l2, l3);
}

// build Bt[n][k] = W(k, n) split into hi/lo (fused Wq|Wk|Wv transpose)
__global__ void cvt_Bt(const float* __restrict__ Wq, const float* __restrict__ Wk,
                       const float* __restrict__ Wv) {
    int idx = blockIdx.x * blockDim.x + threadIdx.x;
    if (idx >= 384 * 128) return;
    int n = idx >> 7, k = idx & 127;
    float v;
    if (n < 128)      v = Wq[k * 128 + n];
    else if (n < 256) v = Wk[k * 128 + (n - 128)];
    else              v = Wv[k * 128 + (n - 256)];
    __nv_bfloat16 h = __float2bfloat16(v);
    g_Bthi[idx] = h;
    g_Btlo[idx] = __float2bfloat16(v - __bfloat162float(h));
}

__global__ void cvt_Wot(const float* __restrict__ Wo) {
    int idx = blockIdx.x * blockDim.x + threadIdx.x;
    if (idx >= 128 * 128) return;
    int n = idx >> 7, k = idx & 127;
    float v = Wo[k * 128 + n];
    __nv_bfloat16 h = __float2bfloat16(v);
    g_Wohi[idx] = h;
    g_Wolo[idx] = __float2bfloat16(v - __bfloat162float(h));
}

// ---------------- bias: fold query into q/k biases ----------------
__global__ void bias_kernel(const float* __restrict__ qe,
                            const float* __restrict__ Wq, const float* __restrict__ bq,
                            const float* __restrict__ Wk, const float* __restrict__ bk,
                            const float* __restrict__ bv) {
    __shared__ float qs[128];
    int j = threadIdx.x;
    qs[j] = qe[j];
    __syncthreads();
    int b = blockIdx.x;
    if (b == 0) {
        float c = bq[j];
        #pragma unroll 4
        for (int i = 0; i < 128; i++) c += qs[i] * Wq[(128 + i) * 128 + j];
        g_biasp[j] = c;
    } else if (b == 1) {
        float c = bk[j];
        #pragma unroll 4
        for (int i = 0; i < 128; i++) c += qs[i] * Wk[(128 + i) * 128 + j];
        g_biasp[128 + j] = c;
    } else {
        g_biasp[256 + j] = bv[j];
    }
}

// ---------------- HMMA split-bf16 GEMM, cp.async double-buffered ----------------
#define SM_STRIDE  40
#define SM_TILE    (128 * SM_STRIDE)
#define TILE_BYTES (SM_TILE * 2)
#define BUF_BYTES  (4 * TILE_BYTES)
#define GEMM_SMEM  (2 * BUF_BYTES)

__global__ __launch_bounds__(256) void gemm_mma(
        const __nv_bfloat16* __restrict__ Ahi, const __nv_bfloat16* __restrict__ Alo,
        const __nv_bfloat16* __restrict__ Bhi, const __nv_bfloat16* __restrict__ Blo,
        const float* __restrict__ bias, float* __restrict__ C, int Cstride,
        __half* __restrict__ KV16, int qkv, int M) {
    extern __shared__ __align__(16) char dsm[];
    __nv_bfloat16* sm = (__nv_bfloat16*)dsm;
    const int tid = threadIdx.x;
    const int wid = tid >> 5, lane = tid & 31;
    const int m0 = blockIdx.x * 128, n0 = blockIdx.y * 128;
    const int wm = (wid & 3) * 32;
    const int wn = (wid >> 2) * 64;
    const uint32_t smb = smem_u32(sm);

    float acc[2][8][4];
    #pragma unroll
    for (int i = 0; i < 2; i++)
        #pragma unroll
        for (int j = 0; j < 8; j++)
            #pragma unroll
            for (int c = 0; c < 4; c++) acc[i][j][c] = 0.f;

    const __nv_bfloat16* tileP[4] = {Ahi, Alo, Bhi, Blo};

    auto stage = [&](int kc, int buf) {
        #pragma unroll
        for (int t = 0; t < 4; t++) {
            const __nv_bfloat16* P = tileP[t];
            const int base_row = (t < 2) ? m0 : n0;
            const bool isA = (t < 2);
            #pragma unroll
            for (int it = 0; it < 2; it++) {
                int idx = tid + it * 256;
                int row = idx >> 2, c8 = idx & 3;
                bool valid = (!isA) || (base_row + row < M);
                int r = valid ? row : 0;
                const void* src = P + (size_t)(base_row + r) * 128 + kc * 32 + c8 * 8;
                uint32_t dst = smb + buf * BUF_BYTES + t * TILE_BYTES
                             + 2 * (row * SM_STRIDE + c8 * 8);
                cp16(dst, src, valid ? 16 : 0);
            }
        }
        CP_COMMIT();
    };

    const int a_row = lane & 15, a_c8 = (lane >> 4);
    const int b_row = (lane & 7) | ((lane >> 4) << 3);
    const int b_c8 = (lane >> 3) & 1;

    stage(0, 0);
    for (int kc = 0; kc < 4; kc++) {
        const int buf = kc & 1;
        if (kc + 1 < 4) {
            stage(kc + 1, buf ^ 1);
            CP_WAIT(1);
        } else {
            CP_WAIT(0);
        }
        __syncthreads();

        const uint32_t bb = smb + buf * BUF_BYTES;
        #pragma unroll
        for (int pass = 0; pass < 3; pass++) {
            const uint32_t tbA = (pass == 2) ? TILE_BYTES : 0;
            const uint32_t tbB = (pass == 1) ? 3u * TILE_BYTES : 2u * TILE_BYTES;
            #pragma unroll
            for (int ks = 0; ks < 32; ks += 16) {
                uint32_t a[2][4], b[8][2];
                #pragma unroll
                for (int mi = 0; mi < 2; mi++) {
                    uint32_t addr = bb + tbA + 2 * ((wm + mi * 16 + a_row) * SM_STRIDE
                                                    + ks + a_c8 * 8);
                    LDSM_X4(a[mi][0], a[mi][1], a[mi][2], a[mi][3], addr);
                }
                #pragma unroll
                for (int nb = 0; nb < 4; nb++) {
                    uint32_t addr = bb + tbB + 2 * ((wn + nb * 16 + b_row) * SM_STRIDE
                                                    + ks + b_c8 * 8);
                    LDSM_X4(b[2 * nb][0], b[2 * nb][1], b[2 * nb + 1][0], b[2 * nb + 1][1], addr);
                }
                #pragma unroll
                for (int mi = 0; mi < 2; mi++)
                    #pragma unroll
                    for (int ni = 0; ni < 8; ni++)
                        MMA16816(acc[mi][ni], a[mi], b[ni]);
            }
        }
        __syncthreads();
    }

    // epilogue
    const int tq = lane >> 2, tr = lane & 3;
    const bool fp16out = (qkv && blockIdx.y > 0);
    const int hbase = (blockIdx.y == 1) ? 0 : 128;
    #pragma unroll
    for (int ni = 0; ni < 8; ni++) {
        const int col = n0 + wn + ni * 8 + tr * 2;
        const float b0 = bias[col], b1 = bias[col + 1];
        #pragma unroll
        for (int mi = 0; mi < 2; mi++) {
            int mlow = m0 + wm + mi * 16 + tq;
            int mhigh = mlow + 8;
            if (fp16out) {
                int lc = col - n0;
                if (mlow < M) {
                    __half2 h = __float22half2_rn(
                        make_float2(acc[mi][ni][0] + b0, acc[mi][ni][1] + b1));
                    *(__half2*)(KV16 + (size_t)mlow * 256 + hbase + lc) = h;
                }
                if (mhigh < M) {
                    __half2 h = __float22half2_rn(
                        make_float2(acc[mi][ni][2] + b0, acc[mi][ni][3] + b1));
                    *(__half2*)(KV16 + (size_t)mhigh * 256 + hbase + lc) = h;
                }
            } else {
                if (mlow < M) {
                    float2 o = make_float2(acc[mi][ni][0] + b0, acc[mi][ni][1] + b1);
                    *(float2*)(C + (size_t)mlow * Cstride + col) = o;
                }
                if (mhigh < M) {
                    float2 o = make_float2(acc[mi][ni][2] + b0, acc[mi][ni][3] + b1);
                    *(float2*)(C + (size_t)mhigh * Cstride + col) = o;
                }
            }
        }
    }
}

// ---------------- counting sort by dst ----------------
__global__ void hist_kernel(const int* __restrict__ dst) {
    int e = blockIdx.x * blockDim.x + threadIdx.x;
    if (e < N_EDGES) atomicAdd(&g_cnt[dst[e]], 1);
}

__global__ __launch_bounds__(1024) void scan1_kernel() {
    __shared__ int ws[32];
    const int t = threadIdx.x, lane = t & 31, wid = t >> 5;
    int i = blockIdx.x * 1024 + t;
    int v = (i < N_NODES) ? g_cnt[i] : 0;
    int x = v;
    #pragma unroll
    for (int d = 1; d < 32; d <<= 1) {
        int y = __shfl_up_sync(0xffffffffu, x, d);
        if (lane >= d) x += y;
    }
    if (lane == 31) ws[wid] = x;
    __syncthreads();
    if (wid == 0) {
        int s = ws[lane];
        #pragma unroll
        for (int d = 1; d < 32; d <<= 1) {
            int y = __shfl_up_sync(0xffffffffu, s, d);
            if (lane >= d) s += y;
        }
        ws[lane] = s;
    }
    __syncthreads();
    int excl = x - v + (wid > 0 ? ws[wid - 1] : 0);
    if (i < N_NODES) g_excl[i] = excl;
    if (t == 1023) g_bsum[blockIdx.x] = ws[31];
}

__global__ void scan2_kernel(int nb) {
    __shared__ int ws[2];
    const int t = threadIdx.x, lane = t & 31, wid = t >> 5;
    int v = (t < nb) ? g_bsum[t] : 0;
    int x = v;
    #pragma unroll
    for (int d = 1; d < 32; d <<= 1) {
        int y = __shfl_up_sync(0xffffffffu, x, d);
        if (lane >= d) x += y;
    }
    if (lane == 31) ws[wid] = x;
    __syncthreads();
    if (wid == 1) x += ws[0];
    g_boff[t] = x - v;
}

__global__ __launch_bounds__(1024) void scan3_kernel() {
    int i = blockIdx.x * 1024 + threadIdx.x;
    if (i < N_NODES) {
        int s = g_excl[i] + g_boff[blockIdx.x];
        g_start[i] = s;
        g_fill[i] = s;
    }
    if (i == 0) g_start[N_NODES] = N_EDGES;
}

__global__ void scatter_kernel(const int* __restrict__ src,
                               const int* __restrict__ dst,
                               const int* __restrict__ typ) {
    int e = blockIdx.x * blockDim.x + threadIdx.x;
    if (e >= N_EDGES) return;
    int d = dst[e];
    int pos = atomicAdd(&g_fill[d], 1);
    g_sorted[pos] = make_int2(src[e], typ[e]);
}

// ---------------- warp-per-dst softmax aggregation (fp16 k/v gather) ----------------
__global__ void agg_kernel(const float* __restrict__ rel) {
    __shared__ float srel[N_REL * 128];
    const int tid = threadIdx.x, wid = tid >> 5, lane = tid & 31;
    for (int i = tid; i < N_REL * 32; i += 256)
        ((float4*)srel)[i] = ((const float4*)rel)[i];
    __syncthreads();

    for (int dst = blockIdx.x * 8 + wid; dst < N_NODES; dst += 8 * gridDim.x) {
        float4 qv = *(const float4*)(g_Qf + (size_t)dst * 128 + lane * 4);
        int beg = g_start[dst], end = g_start[dst + 1];

        float4 acc = make_float4(0.f, 0.f, 0.f, 0.f);
        float sacc = 0.f;

        for (int e0 = beg; e0 < end; e0 += 32) {
            int2 er = make_int2(0, 0);
            if (e0 + lane < end) er = g_sorted[e0 + lane];
            int cnt = min(32, end - e0);
            for (int i = 0; i < cnt; i++) {
                int src = __shfl_sync(0xffffffffu, er.x, i);
                int typ = __shfl_sync(0xffffffffu, er.y, i);
                uint2 kraw = *(const uint2*)(g_KV16 + (size_t)src * 256 + lane * 4);
                uint2 vraw = *(const uint2*)(g_KV16 + (size_t)src * 256 + 128 + lane * 4);
                float4 rb = *(const float4*)&srel[typ * 128 + lane * 4];
                float2 k01 = __half22float2(*(__half2*)&kraw.x);
                float2 k23 = __half22float2(*(__half2*)&kraw.y);
                float p = qv.x * (k01.x + rb.x) + qv.y * (k01.y + rb.y)
                        + qv.z * (k23.x + rb.z) + qv.w * (k23.y + rb.w);
                p += __shfl_xor_sync(0xffffffffu, p, 1);
                p += __shfl_xor_sync(0xffffffffu, p, 2);
                float w = __expf(p * 0.25f);
                float2 v01 = __half22float2(*(__half2*)&vraw.x);
                float2 v23 = __half22float2(*(__half2*)&vraw.y);
                sacc += w;
                acc.x += w * v01.x; acc.y += w * v01.y;
                acc.z += w * v23.x; acc.w += w * v23.y;
            }
        }
        float inv = 1.0f / (sacc + 1e-8f);
        float4 o = make_float4(acc.x * inv, acc.y * inv, acc.z * inv, acc.w * inv);
        __nv_bfloat16 h0 = __float2bfloat16(o.x), h1 = __float2bfloat16(o.y);
        __nv_bfloat16 h2 = __float2bfloat16(o.z), h3 = __float2bfloat16(o.w);
        __nv_bfloat16 l0 = __float2bfloat16(o.x - __bfloat162float(h0));
        __nv_bfloat16 l1 = __float2bfloat16(o.y - __bfloat162float(h1));
        __nv_bfloat16 l2 = __float2bfloat16(o.z - __bfloat162float(h2));
        __nv_bfloat16 l3 = __float2bfloat16(o.w - __bfloat162float(h3));
        __nv_bfloat162* H = (__nv_bfloat162*)(g_AOhi + (size_t)dst * 128 + lane * 4);
        __nv_bfloat162* L = (__nv_bfloat162*)(g_AOlo + (size_t)dst * 128 + lane * 4);
        H[0] = __halves2bfloat162(h0, h1); H[1] = __halves2bfloat162(h2, h3);
        L[0] = __halves2bfloat162(l0, l1); L[1] = __halves2bfloat162(l2, l3);
    }
}

// ---------------- launch ----------------
extern "C" void kernel_launch(void* const* d_in, const int* in_sizes, int n_in,
                              void* d_out, int out_size) {
    const float* node_features = (const float*)d_in[0];
    const float* query_emb     = (const float*)d_in[1];
    const float* rel_emb       = (const float*)d_in[2];
    const float* Wq            = (const float*)d_in[3];
    const float* bq            = (const float*)d_in[4];
    const float* Wk            = (const float*)d_in[5];
    const float* bk            = (const float*)d_in[6];
    const float* Wv            = (const float*)d_in[7];
    const float* bv            = (const float*)d_in[8];
    const float* Wo            = (const float*)d_in[9];
    const float* bo            = (const float*)d_in[10];
    const int*   edge_index    = (const int*)d_in[11];
    const int*   edge_type     = (const int*)d_in[12];
    float* out = (float*)d_out;

    const int* e_src = edge_index;
    const int* e_dst = edge_index + N_EDGES;

    float*  d_Qf;   cudaGetSymbolAddress((void**)&d_Qf,   g_Qf);
    __half* d_KV16; cudaGetSymbolAddress((void**)&d_KV16, g_KV16);
    float*  d_bp;   cudaGetSymbolAddress((void**)&d_bp,   g_biasp);
    int*    d_cnt;  cudaGetSymbolAddress((void**)&d_cnt,  g_cnt);
    __nv_bfloat16 *d_Ahi, *d_Alo, *d_AOhi, *d_AOlo, *d_Bthi, *d_Btlo, *d_Wohi, *d_Wolo;
    cudaGetSymbolAddress((void**)&d_Ahi,  g_Ahi);
    cudaGetSymbolAddress((void**)&d_Alo,  g_Alo);
    cudaGetSymbolAddress((void**)&d_AOhi, g_AOhi);
    cudaGetSymbolAddress((void**)&d_AOlo, g_AOlo);
    cudaGetSymbolAddress((void**)&d_Bthi, g_Bthi);
    cudaGetSymbolAddress((void**)&d_Btlo, g_Btlo);
    cudaGetSymbolAddress((void**)&d_Wohi, g_Wohi);
    cudaGetSymbolAddress((void**)&d_Wolo, g_Wolo);

    static cudaStream_t s2 = nullptr;
    static cudaEvent_t evFork = nullptr, evJoin = nullptr;
    static bool attr_set = false;
    if (!attr_set) {
        cudaFuncSetAttribute(gemm_mma, cudaFuncAttributeMaxDynamicSharedMemorySize,
                             GEMM_SMEM);
        cudaStreamCreateWithFlags(&s2, cudaStreamNonBlocking);
        cudaEventCreateWithFlags(&evFork, cudaEventDisableTiming);
        cudaEventCreateWithFlags(&evJoin, cudaEventDisableTiming);
        attr_set = true;
    }

    // ---- fork: edge-sort branch on s2, projection branch on origin ----
    cudaEventRecord(evFork, 0);
    cudaStreamWaitEvent(s2, evFork, 0);

    // Branch B (s2): counting sort of edges by dst
    const int NB = (N_NODES + 1023) / 1024;  // 49
    cudaMemsetAsync(d_cnt, 0, N_NODES * sizeof(int), s2);
    hist_kernel<<<(N_EDGES + 255) / 256, 256, 0, s2>>>(e_dst);
    scan1_kernel<<<NB, 1024, 0, s2>>>();
    scan2_kernel<<<1, 64, 0, s2>>>(NB);
    scan3_kernel<<<NB, 1024, 0, s2>>>();
    scatter_kernel<<<(N_EDGES + 255) / 256, 256, 0, s2>>>(e_src, e_dst, edge_type);
    cudaEventRecord(evJoin, s2);

    // Branch A (origin): weight prep + QKV projection
    cvt_Bt<<<(384 * 128 + 255) / 256, 256>>>(Wq, Wk, Wv);
    cvt_Wot<<<(128 * 128 + 255) / 256, 256>>>(Wo);
    bias_kernel<<<3, 128>>>(query_emb, Wq, bq, Wk, bk, bv);
    cvt_split4<<<(N_NODES * 128 / 4 + 255) / 256, 256>>>(node_features, d_Ahi, d_Alo,
                                                         N_NODES * 128 / 4);
    {
        dim3 grid((N_NODES + 127) / 128, 3);
        gemm_mma<<<grid, 256, GEMM_SMEM>>>(d_Ahi, d_Alo, d_Bthi, d_Btlo, d_bp,
                                           d_Qf, 128, d_KV16, 1, N_NODES);
    }

    // ---- join: aggregation needs both branches ----
    cudaStreamWaitEvent(0, evJoin, 0);

    agg_kernel<<<1024, 256>>>(rel_emb);

    // output projection: 50000 x 128 (HMMA split-bf16, fp32 out)
    {
        dim3 grid((N_NODES + 127) / 128, 1);
        gemm_mma<<<grid, 256, GEMM_SMEM>>>(d_AOhi, d_AOlo, d_Wohi, d_Wolo, bo,
                                           out, 128, (__half*)nullptr, 0, N_NODES);
    }
}